// round 7
// baseline (speedup 1.0000x reference)
#include <cuda_runtime.h>
#include <cuda_bf16.h>
#include <math.h>
#include <stdint.h>

#define NN 20000        // nodes per type
#define D  256          // feature dim
#define EE 320000       // edges per relation
#define ND (NN * D)

// ---------------- scratch (device globals: no allocation allowed) ----------------
__device__ __align__(16) float g_h0[ND];      // layer1 out, type 0
__device__ __align__(16) float g_h1[ND];      // layer1 out, type 1
__device__ __align__(16) float g_o2[ND];      // layer2 out, type 0 (logits)
__device__ __align__(16) __nv_bfloat16 g_yb0[ND];   // bf16 transformed features
__device__ __align__(16) __nv_bfloat16 g_yb1[ND];
__device__ __align__(16) __nv_bfloat16 g_yb2[ND];
__device__ __align__(16) __nv_bfloat16 g_yb3[ND];
__device__ __align__(16) float g_WT[9][D * D];   // pre-transposed (combined) weights [n][k]
__device__ float g_bc1[2 * D];
__device__ float g_bc2[D];

// CSR state: group 0 = dst-type-0 edges (rel0 tag0, rel2 tag1)  [reused by layer 2]
//            group 1 = dst-type-1 edges (rel1 tag0, rel4 tag1)
__device__ int g_cnt[2][NN];
__device__ int g_off[2][NN + 1];
__device__ int g_cur[2][NN];
__device__ int g_rec[2][2 * EE];

// ---------------- tiny kernels ----------------
__global__ void zero_kernel(float* o) { o[0] = 0.0f; }

__global__ void zero_cnt_kernel() {
    int i = blockIdx.x * blockDim.x + threadIdx.x;
    if (i < 2 * NN) ((int*)g_cnt)[i] = 0;
}

// segment s -> (rel k, group, tag):  s0:(0,0,0)  s1:(2,0,1)  s2:(1,1,0)  s3:(4,1,1)
__device__ __forceinline__ void seg_map(int s, int& k, int& grp, int& tag) {
    switch (s) {
        case 0:  k = 0; grp = 0; tag = 0; break;
        case 1:  k = 2; grp = 0; tag = 1; break;
        case 2:  k = 1; grp = 1; tag = 0; break;
        default: k = 4; grp = 1; tag = 1; break;
    }
}

__global__ void hist_kernel(const int* __restrict__ edges) {
    int idx = blockIdx.x * blockDim.x + threadIdx.x;
    if (idx >= 4 * EE) return;
    int s = idx / EE, e = idx - s * EE;
    int k, grp, tag; seg_map(s, k, grp, tag);
    int dst = edges[k * 2 * EE + EE + e];
    atomicAdd(&g_cnt[grp][dst], 1);
}

__global__ void scan_kernel() {
    const int grp = blockIdx.x;
    const int tid = threadIdx.x;            // 1024
    __shared__ int sh[1024];
    const int CH = (NN + 1023) / 1024;      // 20
    int base = tid * CH;
    int s = 0;
#pragma unroll
    for (int i = 0; i < CH; i++) {
        int idx = base + i;
        if (idx < NN) s += g_cnt[grp][idx];
    }
    sh[tid] = s;
    __syncthreads();
    for (int off = 1; off < 1024; off <<= 1) {
        int v = 0;
        if (tid >= off) v = sh[tid - off];
        __syncthreads();
        if (tid >= off) sh[tid] += v;
        __syncthreads();
    }
    int run = (tid ? sh[tid - 1] : 0);
#pragma unroll
    for (int i = 0; i < CH; i++) {
        int idx = base + i;
        if (idx < NN) {
            g_off[grp][idx] = run;
            g_cur[grp][idx] = run;
            run += g_cnt[grp][idx];
        }
    }
    if (tid == 1023) g_off[grp][NN] = sh[1023];
}

__global__ void fill_kernel(const int* __restrict__ edges) {
    int idx = blockIdx.x * blockDim.x + threadIdx.x;
    if (idx >= 4 * EE) return;
    int s = idx / EE, e = idx - s * EE;
    int k, grp, tag; seg_map(s, k, grp, tag);
    int src = edges[k * 2 * EE + e];
    int dst = edges[k * 2 * EE + EE + e];
    int pos = atomicAdd(&g_cur[grp][dst], 1);
    g_rec[grp][pos] = (int)((unsigned)src | ((unsigned)tag << 31));
}

// Transpose (+ combine root pairs and biases) into g_WT[9][n][k].
//  0:(Wroot1[0]+Wroot1[2])^T  1:(Wroot1[1]+Wroot1[4])^T
//  2:Wrel1[0]^T 3:Wrel1[1]^T 4:Wrel1[2]^T 5:Wrel1[4]^T
//  6:(Wroot2[0]+Wroot2[2])^T  7:Wrel2[0]^T 8:Wrel2[2]^T
__global__ void prep_kernel(const float* __restrict__ Wrel1, const float* __restrict__ brel1,
                            const float* __restrict__ Wroot1, const float* __restrict__ Wrel2,
                            const float* __restrict__ brel2, const float* __restrict__ Wroot2) {
    __shared__ float t[32][33];
    int j = blockIdx.z;
    const float* S0; const float* S1 = nullptr;
    switch (j) {
        case 0:  S0 = Wroot1;             S1 = Wroot1 + 2 * D * D; break;
        case 1:  S0 = Wroot1 + D * D;     S1 = Wroot1 + 4 * D * D; break;
        case 2:  S0 = Wrel1;              break;
        case 3:  S0 = Wrel1 + D * D;      break;
        case 4:  S0 = Wrel1 + 2 * D * D;  break;
        case 5:  S0 = Wrel1 + 4 * D * D;  break;
        case 6:  S0 = Wroot2;             S1 = Wroot2 + 2 * D * D; break;
        case 7:  S0 = Wrel2;              break;
        default: S0 = Wrel2 + 2 * D * D;  break;
    }
    int k0 = blockIdx.y * 32, n0 = blockIdx.x * 32;
    int tx = threadIdx.x, ty = threadIdx.y;     // 32 x 8
#pragma unroll
    for (int r = ty; r < 32; r += 8) {
        float v = S0[(size_t)(k0 + r) * D + n0 + tx];
        if (S1) v += S1[(size_t)(k0 + r) * D + n0 + tx];
        t[r][tx] = v;
    }
    __syncthreads();
    float* WT = g_WT[j];
#pragma unroll
    for (int r = ty; r < 32; r += 8)
        WT[(size_t)(n0 + r) * D + k0 + tx] = t[tx][r];

    if (blockIdx.x == 0 && blockIdx.y == 0 && j == 0) {
        int i = ty * 32 + tx;
        if (i < D) {
            g_bc1[i]     = brel1[i]         + brel1[2 * D + i];
            g_bc1[D + i] = brel1[D + i]     + brel1[4 * D + i];
            g_bc2[i]     = brel2[i]         + brel2[2 * D + i];
        }
    }
}

// ---------------- tf32 mma.sync GEMM: C[M,256] = A[M,256] @ W (+bias) ----------------
// CTA tile 128x128, BK=32. 8 warps 4x2; warp tile 32x64 = 2x8 m16n8k8 frags.

__device__ __forceinline__ uint32_t f2tf32(float v) {
    uint32_t u;
    asm("cvt.rna.tf32.f32 %0, %1;" : "=r"(u) : "f"(v));
    return u;
}

__device__ __forceinline__ void mma_tf32(float* c, const uint32_t* a, const uint32_t* b) {
    asm volatile(
        "mma.sync.aligned.m16n8k8.row.col.f32.tf32.tf32.f32 "
        "{%0,%1,%2,%3}, {%4,%5,%6,%7}, {%8,%9}, {%0,%1,%2,%3};"
        : "+f"(c[0]), "+f"(c[1]), "+f"(c[2]), "+f"(c[3])
        : "r"(a[0]), "r"(a[1]), "r"(a[2]), "r"(a[3]), "r"(b[0]), "r"(b[1]));
}

template <bool RELU, bool BF16OUT>
__device__ __forceinline__ void gemm_body(const float* __restrict__ A,
                                          const float* __restrict__ WT,
                                          const float* __restrict__ bias,
                                          float* __restrict__ Cf,
                                          __nv_bfloat16* __restrict__ Cb) {
    __shared__ float As[128][36];   // [m][k]
    __shared__ float Bs[128][36];   // [n][k]

    const int tid  = threadIdx.x;
    const int wid  = tid >> 5;
    const int lane = tid & 31;
    const int gid  = lane >> 2;
    const int tig  = lane & 3;
    const int m0 = blockIdx.x * 128;
    const int n0 = blockIdx.y * 128;
    const int wm = (wid & 3) * 32;
    const int wn = (wid >> 2) * 64;

    float acc[2][8][4];
#pragma unroll
    for (int mt = 0; mt < 2; mt++)
#pragma unroll
        for (int nt = 0; nt < 8; nt++)
#pragma unroll
            for (int q = 0; q < 4; q++) acc[mt][nt][q] = 0.0f;

    for (int kc = 0; kc < 8; kc++) {
        const int k0g = kc * 32;
#pragma unroll
        for (int i = 0; i < 4; i++) {
            int idx = tid + i * 256;
            int row = idx >> 3;
            int c4  = (idx & 7) << 2;
            float4 v = make_float4(0.f, 0.f, 0.f, 0.f);
            int m = m0 + row;
            if (m < NN) v = *(const float4*)(A + (size_t)m * D + k0g + c4);
            if (RELU) {
                v.x = fmaxf(v.x, 0.f); v.y = fmaxf(v.y, 0.f);
                v.z = fmaxf(v.z, 0.f); v.w = fmaxf(v.w, 0.f);
            }
            As[row][c4 + 0] = __uint_as_float(f2tf32(v.x));
            As[row][c4 + 1] = __uint_as_float(f2tf32(v.y));
            As[row][c4 + 2] = __uint_as_float(f2tf32(v.z));
            As[row][c4 + 3] = __uint_as_float(f2tf32(v.w));
        }
#pragma unroll
        for (int i = 0; i < 4; i++) {
            int idx = tid + i * 256;
            int row = idx >> 3;
            int c4  = (idx & 7) << 2;
            float4 v = *(const float4*)(WT + (size_t)(n0 + row) * D + k0g + c4);
            Bs[row][c4 + 0] = __uint_as_float(f2tf32(v.x));
            Bs[row][c4 + 1] = __uint_as_float(f2tf32(v.y));
            Bs[row][c4 + 2] = __uint_as_float(f2tf32(v.z));
            Bs[row][c4 + 3] = __uint_as_float(f2tf32(v.w));
        }
        __syncthreads();

#pragma unroll
        for (int ks = 0; ks < 4; ks++) {
            const int k0 = ks * 8;
            uint32_t af[2][4], bf[8][2];
#pragma unroll
            for (int mt = 0; mt < 2; mt++) {
                int r = wm + mt * 16 + gid;
                af[mt][0] = __float_as_uint(As[r][k0 + tig]);
                af[mt][1] = __float_as_uint(As[r + 8][k0 + tig]);
                af[mt][2] = __float_as_uint(As[r][k0 + tig + 4]);
                af[mt][3] = __float_as_uint(As[r + 8][k0 + tig + 4]);
            }
#pragma unroll
            for (int nt = 0; nt < 8; nt++) {
                int c = wn + nt * 8 + gid;
                bf[nt][0] = __float_as_uint(Bs[c][k0 + tig]);
                bf[nt][1] = __float_as_uint(Bs[c][k0 + tig + 4]);
            }
#pragma unroll
            for (int mt = 0; mt < 2; mt++)
#pragma unroll
                for (int nt = 0; nt < 8; nt++)
                    mma_tf32(acc[mt][nt], af[mt], bf[nt]);
        }
        __syncthreads();
    }

#pragma unroll
    for (int mt = 0; mt < 2; mt++) {
        int m_lo = m0 + wm + mt * 16 + gid;
        int m_hi = m_lo + 8;
#pragma unroll
        for (int nt = 0; nt < 8; nt++) {
            int n = n0 + wn + nt * 8 + tig * 2;
            if (BF16OUT) {
                if (m_lo < NN)
                    *(__nv_bfloat162*)(Cb + (size_t)m_lo * D + n) =
                        __float22bfloat162_rn(make_float2(acc[mt][nt][0], acc[mt][nt][1]));
                if (m_hi < NN)
                    *(__nv_bfloat162*)(Cb + (size_t)m_hi * D + n) =
                        __float22bfloat162_rn(make_float2(acc[mt][nt][2], acc[mt][nt][3]));
            } else {
                float b0 = bias ? bias[n] : 0.f;
                float b1 = bias ? bias[n + 1] : 0.f;
                if (m_lo < NN)
                    *(float2*)(Cf + (size_t)m_lo * D + n) =
                        make_float2(acc[mt][nt][0] + b0, acc[mt][nt][1] + b1);
                if (m_hi < NN)
                    *(float2*)(Cf + (size_t)m_hi * D + n) =
                        make_float2(acc[mt][nt][2] + b0, acc[mt][nt][3] + b1);
            }
        }
    }
}

// Layer 1 (6 jobs): roots (fp32+bias) + 4 rel GEMMs (bf16 out).
//  z2: x0@Wrel1[0] -> yb0 (grpA tag0)   z3: x0@Wrel1[1] -> yb2 (grpB tag0)
//  z4: x1@Wrel1[2] -> yb1 (grpA tag1)   z5: x2@Wrel1[4] -> yb3 (grpB tag1)
__global__ __launch_bounds__(256, 2) void gemm1_tc(const float* __restrict__ x) {
    switch (blockIdx.z) {
        case 0:  gemm_body<false, false>(x,          g_WT[0], g_bc1,     g_h0, nullptr); break;
        case 1:  gemm_body<false, false>(x + ND,     g_WT[1], g_bc1 + D, g_h1, nullptr); break;
        case 2:  gemm_body<false, true >(x,          g_WT[2], nullptr, nullptr, g_yb0); break;
        case 3:  gemm_body<false, true >(x,          g_WT[3], nullptr, nullptr, g_yb2); break;
        case 4:  gemm_body<false, true >(x + ND,     g_WT[4], nullptr, nullptr, g_yb1); break;
        default: gemm_body<false, true >(x + 2 * ND, g_WT[5], nullptr, nullptr, g_yb3); break;
    }
}

// Layer 2 (3 jobs; only dst type 0 feeds the loss). ReLU fused into A staging.
//  z1: relu(h0)@Wrel2[0] -> yb0 (tag0)   z2: relu(h1)@Wrel2[2] -> yb1 (tag1)
__global__ __launch_bounds__(256, 2) void gemm2_tc() {
    switch (blockIdx.z) {
        case 0:  gemm_body<true, false>(g_h0, g_WT[6], g_bc2, g_o2, nullptr); break;
        case 1:  gemm_body<true, true >(g_h0, g_WT[7], nullptr, nullptr, g_yb0); break;
        default: gemm_body<true, true >(g_h1, g_WT[8], nullptr, nullptr, g_yb1); break;
    }
}

// ---------------- CSR gather: one warp per dst node ----------------
__device__ __forceinline__ void accum_row(float* acc, const __nv_bfloat16* __restrict__ y0,
                                          const __nv_bfloat16* __restrict__ y1,
                                          int rec, int lane) {
    const __nv_bfloat16* yb = (rec < 0) ? y1 : y0;
    int src = rec & 0x7fffffff;
    uint4 v = *(const uint4*)(yb + (size_t)src * D + lane * 8);
    const __nv_bfloat162* p = (const __nv_bfloat162*)&v;
    float2 f0 = __bfloat1622float2(p[0]);
    float2 f1 = __bfloat1622float2(p[1]);
    float2 f2 = __bfloat1622float2(p[2]);
    float2 f3 = __bfloat1622float2(p[3]);
    acc[0] += f0.x; acc[1] += f0.y; acc[2] += f1.x; acc[3] += f1.y;
    acc[4] += f2.x; acc[5] += f2.y; acc[6] += f3.x; acc[7] += f3.y;
}

__device__ __forceinline__ void gather_node(int grp, int node,
                                            const __nv_bfloat16* __restrict__ y0,
                                            const __nv_bfloat16* __restrict__ y1,
                                            float* __restrict__ tgt, int lane) {
    const int* __restrict__ recs = g_rec[grp];
    int beg = g_off[grp][node];
    int end = g_off[grp][node + 1];

    float acc[8] = {0.f, 0.f, 0.f, 0.f, 0.f, 0.f, 0.f, 0.f};

    for (int base = beg; base < end; base += 32) {
        int m = end - base;
        if (m > 32) m = 32;
        int rec = 0;
        if (lane < m) rec = recs[base + lane];
        int j = 0;
        for (; j + 4 <= m; j += 4) {
            int r0 = __shfl_sync(0xFFFFFFFFu, rec, j);
            int r1 = __shfl_sync(0xFFFFFFFFu, rec, j + 1);
            int r2 = __shfl_sync(0xFFFFFFFFu, rec, j + 2);
            int r3 = __shfl_sync(0xFFFFFFFFu, rec, j + 3);
            accum_row(acc, y0, y1, r0, lane);
            accum_row(acc, y0, y1, r1, lane);
            accum_row(acc, y0, y1, r2, lane);
            accum_row(acc, y0, y1, r3, lane);
        }
        for (; j < m; j++) {
            int r = __shfl_sync(0xFFFFFFFFu, rec, j);
            accum_row(acc, y0, y1, r, lane);
        }
    }

    float* tp = tgt + (size_t)node * D + lane * 8;
    float4 a = *(float4*)tp;
    float4 b = *(float4*)(tp + 4);
    a.x += acc[0]; a.y += acc[1]; a.z += acc[2]; a.w += acc[3];
    b.x += acc[4]; b.y += acc[5]; b.z += acc[6]; b.w += acc[7];
    *(float4*)tp = a;
    *(float4*)(tp + 4) = b;
}

__global__ void gather1_kernel() {
    int gw   = (blockIdx.x * blockDim.x + threadIdx.x) >> 5;   // 0..39999
    int lane = threadIdx.x & 31;
    int grp  = gw >= NN;
    int node = gw - grp * NN;
    if (grp == 0) gather_node(0, node, g_yb0, g_yb1, g_h0, lane);
    else          gather_node(1, node, g_yb2, g_yb3, g_h1, lane);
}

__global__ void gather2_kernel() {
    int gw   = (blockIdx.x * blockDim.x + threadIdx.x) >> 5;   // 0..19999
    int lane = threadIdx.x & 31;
    gather_node(0, gw, g_yb0, g_yb1, g_o2, lane);
}

// ---------------- loss: mean_i [ logsumexp(o2[i,:]) - o2[i, y[i]] ] ----------------
__global__ void loss_kernel(const int* __restrict__ y, float* __restrict__ out) {
    int gw   = (blockIdx.x * blockDim.x + threadIdx.x) >> 5;
    int lane = threadIdx.x & 31;
    const float* row = g_o2 + (size_t)gw * D;

    float v[8];
#pragma unroll
    for (int i = 0; i < 8; i++) v[i] = row[lane + 32 * i];

    float m = v[0];
#pragma unroll
    for (int i = 1; i < 8; i++) m = fmaxf(m, v[i]);
#pragma unroll
    for (int o = 16; o; o >>= 1) m = fmaxf(m, __shfl_xor_sync(0xFFFFFFFFu, m, o));

    float s = 0.0f;
#pragma unroll
    for (int i = 0; i < 8; i++) s += expf(v[i] - m);
#pragma unroll
    for (int o = 16; o; o >>= 1) s += __shfl_xor_sync(0xFFFFFFFFu, s, o);

    float nll = (m + logf(s)) - row[y[gw]];

    __shared__ float partial[8];
    if (lane == 0) partial[threadIdx.x >> 5] = nll;
    __syncthreads();
    if (threadIdx.x == 0) {
        float t = 0.0f;
#pragma unroll
        for (int i = 0; i < 8; i++) t += partial[i];
        atomicAdd(out, t * (1.0f / (float)NN));
    }
}

// ---------------- launch ----------------
extern "C" void kernel_launch(void* const* d_in, const int* in_sizes, int n_in,
                              void* d_out, int out_size) {
    const float* x      = (const float*)d_in[0];
    const int*   edges  = (const int*)d_in[1];
    const int*   y      = (const int*)d_in[2];
    const float* Wrel1  = (const float*)d_in[3];
    const float* brel1  = (const float*)d_in[4];
    const float* Wroot1 = (const float*)d_in[5];
    const float* Wrel2  = (const float*)d_in[6];
    const float* brel2  = (const float*)d_in[7];
    const float* Wroot2 = (const float*)d_in[8];
    float* out = (float*)d_out;

    const int MT = (NN + 127) / 128;   // 157 M-tiles

    zero_kernel<<<1, 1>>>(out);

    // CSR build (independent of GEMMs, runs up front)
    zero_cnt_kernel<<<(2 * NN + 255) / 256, 256>>>();
    hist_kernel<<<(4 * EE + 255) / 256, 256>>>(edges);
    scan_kernel<<<2, 1024>>>();
    fill_kernel<<<(4 * EE + 255) / 256, 256>>>(edges);

    prep_kernel<<<dim3(8, 8, 9), dim3(32, 8)>>>(Wrel1, brel1, Wroot1, Wrel2, brel2, Wroot2);

    gemm1_tc<<<dim3(MT, 2, 6), 256>>>(x);
    gather1_kernel<<<(2 * NN * 32) / 256, 256>>>();     // 5000 blocks

    gemm2_tc<<<dim3(MT, 2, 3), 256>>>();
    gather2_kernel<<<(NN * 32) / 256, 256>>>();         // 2500 blocks

    loss_kernel<<<NN / 8, 256>>>(y, out);
}

// round 9
// speedup vs baseline: 1.2331x; 1.2331x over previous
#include <cuda_runtime.h>
#include <cuda_bf16.h>
#include <math.h>
#include <stdint.h>

#define NN 20000        // nodes per type
#define D  256          // feature dim
#define EE 320000       // edges per relation
#define ND (NN * D)
#define NCHUNK 40       // scan chunks per group
#define CHSZ 500        // NN / NCHUNK

// ---------------- scratch (device globals: no allocation allowed) ----------------
__device__ __align__(16) float g_h0[ND];      // layer1 out, type 0
__device__ __align__(16) float g_h1[ND];      // layer1 out, type 1
__device__ __align__(16) float g_o2[ND];      // layer2 out, type 0 (logits)
__device__ __align__(16) __nv_bfloat16 g_yb0[ND];   // bf16 transformed features
__device__ __align__(16) __nv_bfloat16 g_yb1[ND];
__device__ __align__(16) __nv_bfloat16 g_yb2[ND];
__device__ __align__(16) __nv_bfloat16 g_yb3[ND];
__device__ __align__(16) float g_WT[9][D * D];   // pre-transposed (combined) weights [n][k]
__device__ float g_bc1[2 * D];
__device__ float g_bc2[D];

// CSR state: group 0 = dst-type-0 edges (rel0 tag0, rel2 tag1)  [reused by layer 2]
//            group 1 = dst-type-1 edges (rel1 tag0, rel4 tag1)
__device__ int g_cnt[2][NN];
__device__ int g_off[2][NN + 1];
__device__ int g_cur[2][NN];
__device__ int g_rec[2][2 * EE];
__device__ int g_part[2][NCHUNK];
__device__ int g_pscan[2][NCHUNK];   // exclusive scan of partials

// ---------------- tiny kernels ----------------
__global__ void zero_kernel(float* o) { o[0] = 0.0f; }

__global__ void zero_cnt_kernel() {
    int i = blockIdx.x * blockDim.x + threadIdx.x;
    if (i < 2 * NN) ((int*)g_cnt)[i] = 0;
}

// segment s -> (rel k, group, tag):  s0:(0,0,0)  s1:(2,0,1)  s2:(1,1,0)  s3:(4,1,1)
__device__ __forceinline__ void seg_map(int s, int& k, int& grp, int& tag) {
    switch (s) {
        case 0:  k = 0; grp = 0; tag = 0; break;
        case 1:  k = 2; grp = 0; tag = 1; break;
        case 2:  k = 1; grp = 1; tag = 0; break;
        default: k = 4; grp = 1; tag = 1; break;
    }
}

__global__ void hist_kernel(const int* __restrict__ edges) {
    int idx = blockIdx.x * blockDim.x + threadIdx.x;
    if (idx >= 4 * EE) return;
    int s = idx / EE, e = idx - s * EE;
    int k, grp, tag; seg_map(s, k, grp, tag);
    int dst = edges[k * 2 * EE + EE + e];
    atomicAdd(&g_cnt[grp][dst], 1);
}

// 80 blocks: (grp, chunk) -> partial sum of 500 counts
__global__ void scan_part_kernel() {
    int b = blockIdx.x;
    int grp = b / NCHUNK, chunk = b - grp * NCHUNK;
    int t = threadIdx.x;                  // 256
    __shared__ int sh[256];
    int base = chunk * CHSZ;
    int s = 0;
    if (t < CHSZ) s += g_cnt[grp][base + t];
    if (t + 256 < CHSZ) s += g_cnt[grp][base + t + 256];
    sh[t] = s;
    __syncthreads();
#pragma unroll
    for (int off = 128; off; off >>= 1) {
        if (t < off) sh[t] += sh[t + off];
        __syncthreads();
    }
    if (t == 0) g_part[grp][chunk] = sh[0];
}

// 1 block: exclusive scan of the 2x40 partials (per group)
__global__ void scan_mid_kernel() {
    int t = threadIdx.x;                  // 128
    __shared__ int sh[2][NCHUNK];
    if (t < 2 * NCHUNK) ((int*)sh)[t] = ((int*)g_part)[t];
    __syncthreads();
    if (t < 2) {
        int run = 0;
        for (int i = 0; i < NCHUNK; i++) {
            int c = sh[t][i];
            g_pscan[t][i] = run;
            run += c;
        }
        g_off[t][NN] = run;
    }
}

// 80 blocks x 512: block scan of 500 counts + chunk base -> offsets
__global__ void scan_off_kernel() {
    int b = blockIdx.x;
    int grp = b / NCHUNK, chunk = b - grp * NCHUNK;
    int t = threadIdx.x;                  // 512
    __shared__ int sh[512];
    int base = chunk * CHSZ;
    int c = (t < CHSZ) ? g_cnt[grp][base + t] : 0;
    sh[t] = c;
    __syncthreads();
#pragma unroll
    for (int off = 1; off < 512; off <<= 1) {
        int v = (t >= off) ? sh[t - off] : 0;
        __syncthreads();
        sh[t] += v;
        __syncthreads();
    }
    if (t < CHSZ) {
        int o = g_pscan[grp][chunk] + sh[t] - c;   // exclusive
        g_off[grp][base + t] = o;
        g_cur[grp][base + t] = o;
    }
}

__global__ void fill_kernel(const int* __restrict__ edges) {
    int idx = blockIdx.x * blockDim.x + threadIdx.x;
    if (idx >= 4 * EE) return;
    int s = idx / EE, e = idx - s * EE;
    int k, grp, tag; seg_map(s, k, grp, tag);
    int src = edges[k * 2 * EE + e];
    int dst = edges[k * 2 * EE + EE + e];
    int pos = atomicAdd(&g_cur[grp][dst], 1);
    g_rec[grp][pos] = (int)((unsigned)src | ((unsigned)tag << 31));
}

// Transpose (+ combine root pairs and biases) into g_WT[9][n][k].
__global__ void prep_kernel(const float* __restrict__ Wrel1, const float* __restrict__ brel1,
                            const float* __restrict__ Wroot1, const float* __restrict__ Wrel2,
                            const float* __restrict__ brel2, const float* __restrict__ Wroot2) {
    __shared__ float t[32][33];
    int j = blockIdx.z;
    const float* S0; const float* S1 = nullptr;
    switch (j) {
        case 0:  S0 = Wroot1;             S1 = Wroot1 + 2 * D * D; break;
        case 1:  S0 = Wroot1 + D * D;     S1 = Wroot1 + 4 * D * D; break;
        case 2:  S0 = Wrel1;              break;
        case 3:  S0 = Wrel1 + D * D;      break;
        case 4:  S0 = Wrel1 + 2 * D * D;  break;
        case 5:  S0 = Wrel1 + 4 * D * D;  break;
        case 6:  S0 = Wroot2;             S1 = Wroot2 + 2 * D * D; break;
        case 7:  S0 = Wrel2;              break;
        default: S0 = Wrel2 + 2 * D * D;  break;
    }
    int k0 = blockIdx.y * 32, n0 = blockIdx.x * 32;
    int tx = threadIdx.x, ty = threadIdx.y;     // 32 x 8
#pragma unroll
    for (int r = ty; r < 32; r += 8) {
        float v = S0[(size_t)(k0 + r) * D + n0 + tx];
        if (S1) v += S1[(size_t)(k0 + r) * D + n0 + tx];
        t[r][tx] = v;
    }
    __syncthreads();
    float* WT = g_WT[j];
#pragma unroll
    for (int r = ty; r < 32; r += 8)
        WT[(size_t)(n0 + r) * D + k0 + tx] = t[tx][r];

    if (blockIdx.x == 0 && blockIdx.y == 0 && j == 0) {
        int i = ty * 32 + tx;
        if (i < D) {
            g_bc1[i]     = brel1[i]         + brel1[2 * D + i];
            g_bc1[D + i] = brel1[D + i]     + brel1[4 * D + i];
            g_bc2[i]     = brel2[i]         + brel2[2 * D + i];
        }
    }
}

// ---------------- bf16 mma.sync GEMM: C[M,256] = A[M,256] @ W (+bias) ----------------
// CTA tile 128x128, BK=64. 8 warps 4x2; warp tile 32x64 = 2x8 m16n8k16 frags.
// SMEM: bf16-pair words, stride 36 -> fragment banks = 4*gid + tig (conflict-free).

// pack two f32 into a bf16x2 word: low = a, high = b (PTX: cvt d, hi, lo)
__device__ __forceinline__ uint32_t bfpair(float a, float b) {
    uint32_t u;
    asm("cvt.rn.bf16x2.f32 %0, %1, %2;" : "=r"(u) : "f"(b), "f"(a));
    return u;
}

__device__ __forceinline__ void mma_bf16(float* c, const uint32_t* a, const uint32_t* b) {
    asm volatile(
        "mma.sync.aligned.m16n8k16.row.col.f32.bf16.bf16.f32 "
        "{%0,%1,%2,%3}, {%4,%5,%6,%7}, {%8,%9}, {%0,%1,%2,%3};"
        : "+f"(c[0]), "+f"(c[1]), "+f"(c[2]), "+f"(c[3])
        : "r"(a[0]), "r"(a[1]), "r"(a[2]), "r"(a[3]), "r"(b[0]), "r"(b[1]));
}

template <bool RELU, bool BF16OUT>
__device__ __forceinline__ void gemm_body(const float* __restrict__ A,
                                          const float* __restrict__ WT,
                                          const float* __restrict__ bias,
                                          float* __restrict__ Cf,
                                          __nv_bfloat16* __restrict__ Cb) {
    __shared__ uint32_t As[128][36];   // [m][kw], 32 words = 64 k
    __shared__ uint32_t Bs[128][36];   // [n][kw]

    const int tid  = threadIdx.x;
    const int wid  = tid >> 5;
    const int lane = tid & 31;
    const int gid  = lane >> 2;
    const int tig  = lane & 3;
    const int m0 = blockIdx.x * 128;
    const int n0 = blockIdx.y * 128;
    const int wm = (wid & 3) * 32;
    const int wn = (wid >> 2) * 64;

    float acc[2][8][4];
#pragma unroll
    for (int mt = 0; mt < 2; mt++)
#pragma unroll
        for (int nt = 0; nt < 8; nt++)
#pragma unroll
            for (int q = 0; q < 4; q++) acc[mt][nt][q] = 0.0f;

    for (int kc = 0; kc < 4; kc++) {
        const int k0g = kc * 64;
        // ---- stage A tile: 128 rows x 64 floats (2048 float4, 8/thread) ----
#pragma unroll
        for (int i = 0; i < 8; i++) {
            int idx = tid + i * 256;
            int row = idx >> 4;             // 0..127
            int c4  = (idx & 15) << 2;      // float offset 0..60
            float4 v = make_float4(0.f, 0.f, 0.f, 0.f);
            int m = m0 + row;
            if (m < NN) v = *(const float4*)(A + (size_t)m * D + k0g + c4);
            if (RELU) {
                v.x = fmaxf(v.x, 0.f); v.y = fmaxf(v.y, 0.f);
                v.z = fmaxf(v.z, 0.f); v.w = fmaxf(v.w, 0.f);
            }
            As[row][(c4 >> 1) + 0] = bfpair(v.x, v.y);
            As[row][(c4 >> 1) + 1] = bfpair(v.z, v.w);
        }
        // ---- stage B tile: 128 n-rows x 64 k ----
#pragma unroll
        for (int i = 0; i < 8; i++) {
            int idx = tid + i * 256;
            int row = idx >> 4;
            int c4  = (idx & 15) << 2;
            float4 v = *(const float4*)(WT + (size_t)(n0 + row) * D + k0g + c4);
            Bs[row][(c4 >> 1) + 0] = bfpair(v.x, v.y);
            Bs[row][(c4 >> 1) + 1] = bfpair(v.z, v.w);
        }
        __syncthreads();

#pragma unroll
        for (int ks = 0; ks < 4; ks++) {
            const int kw0 = ks * 8;         // k-step of 16 values = 8 words
            uint32_t af[2][4], bf[8][2];
#pragma unroll
            for (int mt = 0; mt < 2; mt++) {
                int r = wm + mt * 16 + gid;
                af[mt][0] = As[r][kw0 + tig];
                af[mt][1] = As[r + 8][kw0 + tig];
                af[mt][2] = As[r][kw0 + tig + 4];
                af[mt][3] = As[r + 8][kw0 + tig + 4];
            }
#pragma unroll
            for (int nt = 0; nt < 8; nt++) {
                int c = wn + nt * 8 + gid;
                bf[nt][0] = Bs[c][kw0 + tig];
                bf[nt][1] = Bs[c][kw0 + tig + 4];
            }
#pragma unroll
            for (int mt = 0; mt < 2; mt++)
#pragma unroll
                for (int nt = 0; nt < 8; nt++)
                    mma_bf16(acc[mt][nt], af[mt], bf[nt]);
        }
        __syncthreads();
    }

#pragma unroll
    for (int mt = 0; mt < 2; mt++) {
        int m_lo = m0 + wm + mt * 16 + gid;
        int m_hi = m_lo + 8;
#pragma unroll
        for (int nt = 0; nt < 8; nt++) {
            int n = n0 + wn + nt * 8 + tig * 2;
            if (BF16OUT) {
                if (m_lo < NN)
                    *(uint32_t*)(Cb + (size_t)m_lo * D + n) =
                        bfpair(acc[mt][nt][0], acc[mt][nt][1]);
                if (m_hi < NN)
                    *(uint32_t*)(Cb + (size_t)m_hi * D + n) =
                        bfpair(acc[mt][nt][2], acc[mt][nt][3]);
            } else {
                float b0 = bias ? bias[n] : 0.f;
                float b1 = bias ? bias[n + 1] : 0.f;
                if (m_lo < NN)
                    *(float2*)(Cf + (size_t)m_lo * D + n) =
                        make_float2(acc[mt][nt][0] + b0, acc[mt][nt][1] + b1);
                if (m_hi < NN)
                    *(float2*)(Cf + (size_t)m_hi * D + n) =
                        make_float2(acc[mt][nt][2] + b0, acc[mt][nt][3] + b1);
            }
        }
    }
}

// Layer 1 (6 jobs): roots (fp32+bias) + 4 rel GEMMs (bf16 out).
__global__ __launch_bounds__(256, 2) void gemm1_tc(const float* __restrict__ x) {
    switch (blockIdx.z) {
        case 0:  gemm_body<false, false>(x,          g_WT[0], g_bc1,     g_h0, nullptr); break;
        case 1:  gemm_body<false, false>(x + ND,     g_WT[1], g_bc1 + D, g_h1, nullptr); break;
        case 2:  gemm_body<false, true >(x,          g_WT[2], nullptr, nullptr, g_yb0); break;
        case 3:  gemm_body<false, true >(x,          g_WT[3], nullptr, nullptr, g_yb2); break;
        case 4:  gemm_body<false, true >(x + ND,     g_WT[4], nullptr, nullptr, g_yb1); break;
        default: gemm_body<false, true >(x + 2 * ND, g_WT[5], nullptr, nullptr, g_yb3); break;
    }
}

// Layer 2 (3 jobs; only dst type 0 feeds the loss). ReLU fused into A staging.
__global__ __launch_bounds__(256, 2) void gemm2_tc() {
    switch (blockIdx.z) {
        case 0:  gemm_body<true, false>(g_h0, g_WT[6], g_bc2, g_o2, nullptr); break;
        case 1:  gemm_body<true, true >(g_h0, g_WT[7], nullptr, nullptr, g_yb0); break;
        default: gemm_body<true, true >(g_h1, g_WT[8], nullptr, nullptr, g_yb1); break;
    }
}

// ---------------- CSR gather: one warp per dst node ----------------
__device__ __forceinline__ void accum_row(float* acc, const __nv_bfloat16* __restrict__ y0,
                                          const __nv_bfloat16* __restrict__ y1,
                                          int rec, int lane) {
    const __nv_bfloat16* yb = (rec < 0) ? y1 : y0;
    int src = rec & 0x7fffffff;
    uint4 v = *(const uint4*)(yb + (size_t)src * D + lane * 8);
    const __nv_bfloat162* p = (const __nv_bfloat162*)&v;
    float2 f0 = __bfloat1622float2(p[0]);
    float2 f1 = __bfloat1622float2(p[1]);
    float2 f2 = __bfloat1622float2(p[2]);
    float2 f3 = __bfloat1622float2(p[3]);
    acc[0] += f0.x; acc[1] += f0.y; acc[2] += f1.x; acc[3] += f1.y;
    acc[4] += f2.x; acc[5] += f2.y; acc[6] += f3.x; acc[7] += f3.y;
}

__device__ __forceinline__ void gather_node(int grp, int node,
                                            const __nv_bfloat16* __restrict__ y0,
                                            const __nv_bfloat16* __restrict__ y1,
                                            float* __restrict__ tgt, int lane) {
    const int* __restrict__ recs = g_rec[grp];
    int beg = g_off[grp][node];
    int end = g_off[grp][node + 1];

    float acc[8] = {0.f, 0.f, 0.f, 0.f, 0.f, 0.f, 0.f, 0.f};

    for (int base = beg; base < end; base += 32) {
        int m = end - base;
        if (m > 32) m = 32;
        int rec = 0;
        if (lane < m) rec = recs[base + lane];
        int j = 0;
        for (; j + 4 <= m; j += 4) {
            int r0 = __shfl_sync(0xFFFFFFFFu, rec, j);
            int r1 = __shfl_sync(0xFFFFFFFFu, rec, j + 1);
            int r2 = __shfl_sync(0xFFFFFFFFu, rec, j + 2);
            int r3 = __shfl_sync(0xFFFFFFFFu, rec, j + 3);
            accum_row(acc, y0, y1, r0, lane);
            accum_row(acc, y0, y1, r1, lane);
            accum_row(acc, y0, y1, r2, lane);
            accum_row(acc, y0, y1, r3, lane);
        }
        for (; j < m; j++) {
            int r = __shfl_sync(0xFFFFFFFFu, rec, j);
            accum_row(acc, y0, y1, r, lane);
        }
    }

    float* tp = tgt + (size_t)node * D + lane * 8;
    float4 a = *(float4*)tp;
    float4 b = *(float4*)(tp + 4);
    a.x += acc[0]; a.y += acc[1]; a.z += acc[2]; a.w += acc[3];
    b.x += acc[4]; b.y += acc[5]; b.z += acc[6]; b.w += acc[7];
    *(float4*)tp = a;
    *(float4*)(tp + 4) = b;
}

__global__ void gather1_kernel() {
    int gw   = (blockIdx.x * blockDim.x + threadIdx.x) >> 5;   // 0..39999
    int lane = threadIdx.x & 31;
    int grp  = gw >= NN;
    int node = gw - grp * NN;
    if (grp == 0) gather_node(0, node, g_yb0, g_yb1, g_h0, lane);
    else          gather_node(1, node, g_yb2, g_yb3, g_h1, lane);
}

__global__ void gather2_kernel() {
    int gw   = (blockIdx.x * blockDim.x + threadIdx.x) >> 5;   // 0..19999
    int lane = threadIdx.x & 31;
    gather_node(0, gw, g_yb0, g_yb1, g_o2, lane);
}

// ---------------- loss: mean_i [ logsumexp(o2[i,:]) - o2[i, y[i]] ] ----------------
__global__ void loss_kernel(const int* __restrict__ y, float* __restrict__ out) {
    int gw   = (blockIdx.x * blockDim.x + threadIdx.x) >> 5;
    int lane = threadIdx.x & 31;
    const float* row = g_o2 + (size_t)gw * D;

    float v[8];
#pragma unroll
    for (int i = 0; i < 8; i++) v[i] = row[lane + 32 * i];

    float m = v[0];
#pragma unroll
    for (int i = 1; i < 8; i++) m = fmaxf(m, v[i]);
#pragma unroll
    for (int o = 16; o; o >>= 1) m = fmaxf(m, __shfl_xor_sync(0xFFFFFFFFu, m, o));

    float s = 0.0f;
#pragma unroll
    for (int i = 0; i < 8; i++) s += expf(v[i] - m);
#pragma unroll
    for (int o = 16; o; o >>= 1) s += __shfl_xor_sync(0xFFFFFFFFu, s, o);

    float nll = (m + logf(s)) - row[y[gw]];

    __shared__ float partial[8];
    if (lane == 0) partial[threadIdx.x >> 5] = nll;
    __syncthreads();
    if (threadIdx.x == 0) {
        float t = 0.0f;
#pragma unroll
        for (int i = 0; i < 8; i++) t += partial[i];
        atomicAdd(out, t * (1.0f / (float)NN));
    }
}

// ---------------- launch ----------------
extern "C" void kernel_launch(void* const* d_in, const int* in_sizes, int n_in,
                              void* d_out, int out_size) {
    const float* x      = (const float*)d_in[0];
    const int*   edges  = (const int*)d_in[1];
    const int*   y      = (const int*)d_in[2];
    const float* Wrel1  = (const float*)d_in[3];
    const float* brel1  = (const float*)d_in[4];
    const float* Wroot1 = (const float*)d_in[5];
    const float* Wrel2  = (const float*)d_in[6];
    const float* brel2  = (const float*)d_in[7];
    const float* Wroot2 = (const float*)d_in[8];
    float* out = (float*)d_out;

    const int MT = (NN + 127) / 128;   // 157 M-tiles

    zero_kernel<<<1, 1>>>(out);

    // CSR build (independent of GEMMs, runs up front)
    zero_cnt_kernel<<<(2 * NN + 255) / 256, 256>>>();
    hist_kernel<<<(4 * EE + 255) / 256, 256>>>(edges);
    scan_part_kernel<<<2 * NCHUNK, 256>>>();
    scan_mid_kernel<<<1, 128>>>();
    scan_off_kernel<<<2 * NCHUNK, 512>>>();
    fill_kernel<<<(4 * EE + 255) / 256, 256>>>(edges);

    prep_kernel<<<dim3(8, 8, 9), dim3(32, 8)>>>(Wrel1, brel1, Wroot1, Wrel2, brel2, Wroot2);

    gemm1_tc<<<dim3(MT, 2, 6), 256>>>(x);
    gather1_kernel<<<(2 * NN * 32) / 256, 256>>>();     // 5000 blocks

    gemm2_tc<<<dim3(MT, 2, 3), 256>>>();
    gather2_kernel<<<(NN * 32) / 256, 256>>>();         // 2500 blocks

    loss_kernel<<<NN / 8, 256>>>(y, out);
}

// round 10
// speedup vs baseline: 1.2978x; 1.0525x over previous
#include <cuda_runtime.h>
#include <cuda_bf16.h>
#include <math.h>
#include <stdint.h>

#define NN 20000        // nodes per type
#define D  256          // feature dim
#define EE 320000       // edges per relation
#define ND (NN * D)
#define CAP 96          // bucket capacity per node per group (Poisson(32) + 11 sigma)

// ---------------- scratch (device globals: no allocation allowed) ----------------
__device__ __align__(16) float g_h0[ND];      // layer1 out, type 0
__device__ __align__(16) float g_h1[ND];      // layer1 out, type 1
__device__ __align__(16) float g_o2[ND];      // layer2 root part, type 0
__device__ __align__(16) __nv_bfloat16 g_yb0[ND];   // bf16 transformed features
__device__ __align__(16) __nv_bfloat16 g_yb1[ND];
__device__ __align__(16) __nv_bfloat16 g_yb2[ND];
__device__ __align__(16) __nv_bfloat16 g_yb3[ND];
__device__ __align__(16) float g_WT[9][D * D];   // pre-transposed (combined) weights [n][k]
__device__ float g_bc1[2 * D];
__device__ float g_bc2[D];

// Bucketed edge lists: group 0 = dst-type-0 (rel0 tag0, rel2 tag1) [reused by layer 2]
//                      group 1 = dst-type-1 (rel1 tag0, rel4 tag1)
__device__ int g_cnt[2][NN];
__device__ int g_rec[2][NN * CAP];

// ---------------- tiny kernels ----------------
// zero counters + the output scalar
__global__ void zero_cnt_kernel(float* o) {
    int i = blockIdx.x * blockDim.x + threadIdx.x;
    if (i < 2 * NN) ((int*)g_cnt)[i] = 0;
    if (i == 0) o[0] = 0.0f;
}

// segment s -> (rel k, group, tag):  s0:(0,0,0)  s1:(2,0,1)  s2:(1,1,0)  s3:(4,1,1)
__device__ __forceinline__ void seg_map(int s, int& k, int& grp, int& tag) {
    switch (s) {
        case 0:  k = 0; grp = 0; tag = 0; break;
        case 1:  k = 2; grp = 0; tag = 1; break;
        case 2:  k = 1; grp = 1; tag = 0; break;
        default: k = 4; grp = 1; tag = 1; break;
    }
}

// single pass: scatter edges into per-dst buckets
__global__ void fill_kernel(const int* __restrict__ edges) {
    int idx = blockIdx.x * blockDim.x + threadIdx.x;
    if (idx >= 4 * EE) return;
    int s = idx / EE, e = idx - s * EE;
    int k, grp, tag; seg_map(s, k, grp, tag);
    int src = edges[k * 2 * EE + e];
    int dst = edges[k * 2 * EE + EE + e];
    int pos = atomicAdd(&g_cnt[grp][dst], 1);
    if (pos < CAP)
        g_rec[grp][dst * CAP + pos] = (int)((unsigned)src | ((unsigned)tag << 31));
}

// Transpose (+ combine root pairs and biases) into g_WT[9][n][k].
__global__ void prep_kernel(const float* __restrict__ Wrel1, const float* __restrict__ brel1,
                            const float* __restrict__ Wroot1, const float* __restrict__ Wrel2,
                            const float* __restrict__ brel2, const float* __restrict__ Wroot2) {
    __shared__ float t[32][33];
    int j = blockIdx.z;
    const float* S0; const float* S1 = nullptr;
    switch (j) {
        case 0:  S0 = Wroot1;             S1 = Wroot1 + 2 * D * D; break;
        case 1:  S0 = Wroot1 + D * D;     S1 = Wroot1 + 4 * D * D; break;
        case 2:  S0 = Wrel1;              break;
        case 3:  S0 = Wrel1 + D * D;      break;
        case 4:  S0 = Wrel1 + 2 * D * D;  break;
        case 5:  S0 = Wrel1 + 4 * D * D;  break;
        case 6:  S0 = Wroot2;             S1 = Wroot2 + 2 * D * D; break;
        case 7:  S0 = Wrel2;              break;
        default: S0 = Wrel2 + 2 * D * D;  break;
    }
    int k0 = blockIdx.y * 32, n0 = blockIdx.x * 32;
    int tx = threadIdx.x, ty = threadIdx.y;     // 32 x 8
#pragma unroll
    for (int r = ty; r < 32; r += 8) {
        float v = S0[(size_t)(k0 + r) * D + n0 + tx];
        if (S1) v += S1[(size_t)(k0 + r) * D + n0 + tx];
        t[r][tx] = v;
    }
    __syncthreads();
    float* WT = g_WT[j];
#pragma unroll
    for (int r = ty; r < 32; r += 8)
        WT[(size_t)(n0 + r) * D + k0 + tx] = t[tx][r];

    if (blockIdx.x == 0 && blockIdx.y == 0 && j == 0) {
        int i = ty * 32 + tx;
        if (i < D) {
            g_bc1[i]     = brel1[i]         + brel1[2 * D + i];
            g_bc1[D + i] = brel1[D + i]     + brel1[4 * D + i];
            g_bc2[i]     = brel2[i]         + brel2[2 * D + i];
        }
    }
}

// ---------------- bf16 mma.sync GEMM: C[M,256] = A[M,256] @ W (+bias) ----------------
// CTA tile 128x128, BK=64. 8 warps 4x2; warp tile 32x64 = 2x8 m16n8k16 frags.
// SMEM: bf16-pair words, stride 36 -> fragment banks = 4*gid + tig (conflict-free).

// pack two f32 into a bf16x2 word: low = a, high = b (PTX: cvt d, hi, lo)
__device__ __forceinline__ uint32_t bfpair(float a, float b) {
    uint32_t u;
    asm("cvt.rn.bf16x2.f32 %0, %1, %2;" : "=r"(u) : "f"(b), "f"(a));
    return u;
}

__device__ __forceinline__ void mma_bf16(float* c, const uint32_t* a, const uint32_t* b) {
    asm volatile(
        "mma.sync.aligned.m16n8k16.row.col.f32.bf16.bf16.f32 "
        "{%0,%1,%2,%3}, {%4,%5,%6,%7}, {%8,%9}, {%0,%1,%2,%3};"
        : "+f"(c[0]), "+f"(c[1]), "+f"(c[2]), "+f"(c[3])
        : "r"(a[0]), "r"(a[1]), "r"(a[2]), "r"(a[3]), "r"(b[0]), "r"(b[1]));
}

template <bool RELU, bool BF16OUT>
__device__ __forceinline__ void gemm_body(const float* __restrict__ A,
                                          const float* __restrict__ WT,
                                          const float* __restrict__ bias,
                                          float* __restrict__ Cf,
                                          __nv_bfloat16* __restrict__ Cb) {
    __shared__ uint32_t As[128][36];   // [m][kw], 32 words = 64 k
    __shared__ uint32_t Bs[128][36];   // [n][kw]

    const int tid  = threadIdx.x;
    const int wid  = tid >> 5;
    const int lane = tid & 31;
    const int gid  = lane >> 2;
    const int tig  = lane & 3;
    const int m0 = blockIdx.x * 128;
    const int n0 = blockIdx.y * 128;
    const int wm = (wid & 3) * 32;
    const int wn = (wid >> 2) * 64;

    float acc[2][8][4];
#pragma unroll
    for (int mt = 0; mt < 2; mt++)
#pragma unroll
        for (int nt = 0; nt < 8; nt++)
#pragma unroll
            for (int q = 0; q < 4; q++) acc[mt][nt][q] = 0.0f;

    for (int kc = 0; kc < 4; kc++) {
        const int k0g = kc * 64;
        // ---- stage A tile: 128 rows x 64 floats (2048 float4, 8/thread) ----
#pragma unroll
        for (int i = 0; i < 8; i++) {
            int idx = tid + i * 256;
            int row = idx >> 4;             // 0..127
            int c4  = (idx & 15) << 2;      // float offset 0..60
            float4 v = make_float4(0.f, 0.f, 0.f, 0.f);
            int m = m0 + row;
            if (m < NN) v = *(const float4*)(A + (size_t)m * D + k0g + c4);
            if (RELU) {
                v.x = fmaxf(v.x, 0.f); v.y = fmaxf(v.y, 0.f);
                v.z = fmaxf(v.z, 0.f); v.w = fmaxf(v.w, 0.f);
            }
            As[row][(c4 >> 1) + 0] = bfpair(v.x, v.y);
            As[row][(c4 >> 1) + 1] = bfpair(v.z, v.w);
        }
        // ---- stage B tile: 128 n-rows x 64 k ----
#pragma unroll
        for (int i = 0; i < 8; i++) {
            int idx = tid + i * 256;
            int row = idx >> 4;
            int c4  = (idx & 15) << 2;
            float4 v = *(const float4*)(WT + (size_t)(n0 + row) * D + k0g + c4);
            Bs[row][(c4 >> 1) + 0] = bfpair(v.x, v.y);
            Bs[row][(c4 >> 1) + 1] = bfpair(v.z, v.w);
        }
        __syncthreads();

#pragma unroll
        for (int ks = 0; ks < 4; ks++) {
            const int kw0 = ks * 8;         // k-step of 16 values = 8 words
            uint32_t af[2][4], bf[8][2];
#pragma unroll
            for (int mt = 0; mt < 2; mt++) {
                int r = wm + mt * 16 + gid;
                af[mt][0] = As[r][kw0 + tig];
                af[mt][1] = As[r + 8][kw0 + tig];
                af[mt][2] = As[r][kw0 + tig + 4];
                af[mt][3] = As[r + 8][kw0 + tig + 4];
            }
#pragma unroll
            for (int nt = 0; nt < 8; nt++) {
                int c = wn + nt * 8 + gid;
                bf[nt][0] = Bs[c][kw0 + tig];
                bf[nt][1] = Bs[c][kw0 + tig + 4];
            }
#pragma unroll
            for (int mt = 0; mt < 2; mt++)
#pragma unroll
                for (int nt = 0; nt < 8; nt++)
                    mma_bf16(acc[mt][nt], af[mt], bf[nt]);
        }
        __syncthreads();
    }

#pragma unroll
    for (int mt = 0; mt < 2; mt++) {
        int m_lo = m0 + wm + mt * 16 + gid;
        int m_hi = m_lo + 8;
#pragma unroll
        for (int nt = 0; nt < 8; nt++) {
            int n = n0 + wn + nt * 8 + tig * 2;
            if (BF16OUT) {
                if (m_lo < NN)
                    *(uint32_t*)(Cb + (size_t)m_lo * D + n) =
                        bfpair(acc[mt][nt][0], acc[mt][nt][1]);
                if (m_hi < NN)
                    *(uint32_t*)(Cb + (size_t)m_hi * D + n) =
                        bfpair(acc[mt][nt][2], acc[mt][nt][3]);
            } else {
                float b0 = bias ? bias[n] : 0.f;
                float b1 = bias ? bias[n + 1] : 0.f;
                if (m_lo < NN)
                    *(float2*)(Cf + (size_t)m_lo * D + n) =
                        make_float2(acc[mt][nt][0] + b0, acc[mt][nt][1] + b1);
                if (m_hi < NN)
                    *(float2*)(Cf + (size_t)m_hi * D + n) =
                        make_float2(acc[mt][nt][2] + b0, acc[mt][nt][3] + b1);
            }
        }
    }
}

// Layer 1 (6 jobs): roots (fp32+bias) + 4 rel GEMMs (bf16 out).
__global__ __launch_bounds__(256, 2) void gemm1_tc(const float* __restrict__ x) {
    switch (blockIdx.z) {
        case 0:  gemm_body<false, false>(x,          g_WT[0], g_bc1,     g_h0, nullptr); break;
        case 1:  gemm_body<false, false>(x + ND,     g_WT[1], g_bc1 + D, g_h1, nullptr); break;
        case 2:  gemm_body<false, true >(x,          g_WT[2], nullptr, nullptr, g_yb0); break;
        case 3:  gemm_body<false, true >(x,          g_WT[3], nullptr, nullptr, g_yb2); break;
        case 4:  gemm_body<false, true >(x + ND,     g_WT[4], nullptr, nullptr, g_yb1); break;
        default: gemm_body<false, true >(x + 2 * ND, g_WT[5], nullptr, nullptr, g_yb3); break;
    }
}

// Layer 2 (3 jobs; only dst type 0 feeds the loss). ReLU fused into A staging.
__global__ __launch_bounds__(256, 2) void gemm2_tc() {
    switch (blockIdx.z) {
        case 0:  gemm_body<true, false>(g_h0, g_WT[6], g_bc2, g_o2, nullptr); break;
        case 1:  gemm_body<true, true >(g_h0, g_WT[7], nullptr, nullptr, g_yb0); break;
        default: gemm_body<true, true >(g_h1, g_WT[8], nullptr, nullptr, g_yb1); break;
    }
}

// ---------------- bucket gather: one warp per dst node ----------------
__device__ __forceinline__ void accum_row(float* acc, const __nv_bfloat16* __restrict__ y0,
                                          const __nv_bfloat16* __restrict__ y1,
                                          int rec, int lane) {
    const __nv_bfloat16* yb = (rec < 0) ? y1 : y0;
    int src = rec & 0x7fffffff;
    uint4 v = *(const uint4*)(yb + (size_t)src * D + lane * 8);
    const __nv_bfloat162* p = (const __nv_bfloat162*)&v;
    float2 f0 = __bfloat1622float2(p[0]);
    float2 f1 = __bfloat1622float2(p[1]);
    float2 f2 = __bfloat1622float2(p[2]);
    float2 f3 = __bfloat1622float2(p[3]);
    acc[0] += f0.x; acc[1] += f0.y; acc[2] += f1.x; acc[3] += f1.y;
    acc[4] += f2.x; acc[5] += f2.y; acc[6] += f3.x; acc[7] += f3.y;
}

// accumulate the bucket of (grp, node) into acc[8] (lane owns cols lane*8..lane*8+7)
__device__ __forceinline__ void gather_accum(int grp, int node,
                                             const __nv_bfloat16* __restrict__ y0,
                                             const __nv_bfloat16* __restrict__ y1,
                                             float* acc, int lane) {
    const int* __restrict__ recs = g_rec[grp] + node * CAP;
    int cnt = g_cnt[grp][node];
    if (cnt > CAP) cnt = CAP;

    for (int base = 0; base < cnt; base += 32) {
        int m = cnt - base;
        if (m > 32) m = 32;
        int rec = 0;
        if (lane < m) rec = recs[base + lane];
        int j = 0;
        for (; j + 4 <= m; j += 4) {
            int r0 = __shfl_sync(0xFFFFFFFFu, rec, j);
            int r1 = __shfl_sync(0xFFFFFFFFu, rec, j + 1);
            int r2 = __shfl_sync(0xFFFFFFFFu, rec, j + 2);
            int r3 = __shfl_sync(0xFFFFFFFFu, rec, j + 3);
            accum_row(acc, y0, y1, r0, lane);
            accum_row(acc, y0, y1, r1, lane);
            accum_row(acc, y0, y1, r2, lane);
            accum_row(acc, y0, y1, r3, lane);
        }
        for (; j < m; j++) {
            int r = __shfl_sync(0xFFFFFFFFu, rec, j);
            accum_row(acc, y0, y1, r, lane);
        }
    }
}

__global__ void gather1_kernel() {
    int gw   = (blockIdx.x * blockDim.x + threadIdx.x) >> 5;   // 0..39999
    int lane = threadIdx.x & 31;
    int grp  = gw >= NN;
    int node = gw - grp * NN;

    float acc[8] = {0.f, 0.f, 0.f, 0.f, 0.f, 0.f, 0.f, 0.f};
    if (grp == 0) gather_accum(0, node, g_yb0, g_yb1, acc, lane);
    else          gather_accum(1, node, g_yb2, g_yb3, acc, lane);

    float* tgt = grp == 0 ? g_h0 : g_h1;
    float* tp = tgt + (size_t)node * D + lane * 8;
    float4 a = *(float4*)tp;
    float4 b = *(float4*)(tp + 4);
    a.x += acc[0]; a.y += acc[1]; a.z += acc[2]; a.w += acc[3];
    b.x += acc[4]; b.y += acc[5]; b.z += acc[6]; b.w += acc[7];
    *(float4*)tp = a;
    *(float4*)(tp + 4) = b;
}

// ---------------- fused layer-2 gather + loss ----------------
// warp per row: agg = gather(group0 over yb0/yb1); row = o2_root + agg;
// nll = logsumexp(row) - row[label]; block-sum -> atomicAdd.
__global__ void gather2_loss_kernel(const int* __restrict__ y, float* __restrict__ out) {
    int gw   = (blockIdx.x * blockDim.x + threadIdx.x) >> 5;   // 0..19999
    int lane = threadIdx.x & 31;

    float acc[8] = {0.f, 0.f, 0.f, 0.f, 0.f, 0.f, 0.f, 0.f};
    gather_accum(0, gw, g_yb0, g_yb1, acc, lane);

    const float* rp = g_o2 + (size_t)gw * D + lane * 8;
    float4 a = *(const float4*)rp;
    float4 b = *(const float4*)(rp + 4);
    float v[8];
    v[0] = a.x + acc[0]; v[1] = a.y + acc[1]; v[2] = a.z + acc[2]; v[3] = a.w + acc[3];
    v[4] = b.x + acc[4]; v[5] = b.y + acc[5]; v[6] = b.z + acc[6]; v[7] = b.w + acc[7];

    float m = v[0];
#pragma unroll
    for (int i = 1; i < 8; i++) m = fmaxf(m, v[i]);
#pragma unroll
    for (int o = 16; o; o >>= 1) m = fmaxf(m, __shfl_xor_sync(0xFFFFFFFFu, m, o));

    float s = 0.0f;
#pragma unroll
    for (int i = 0; i < 8; i++) s += expf(v[i] - m);
#pragma unroll
    for (int o = 16; o; o >>= 1) s += __shfl_xor_sync(0xFFFFFFFFu, s, o);

    int yy = y[gw];
    float tv = v[0];
#pragma unroll
    for (int j = 1; j < 8; j++) tv = ((yy & 7) == j) ? v[j] : tv;
    float target = __shfl_sync(0xFFFFFFFFu, tv, yy >> 3);

    float nll = (m + logf(s)) - target;

    __shared__ float partial[8];
    if (lane == 0) partial[threadIdx.x >> 5] = nll;
    __syncthreads();
    if (threadIdx.x == 0) {
        float t = 0.0f;
#pragma unroll
        for (int i = 0; i < 8; i++) t += partial[i];
        atomicAdd(out, t * (1.0f / (float)NN));
    }
}

// ---------------- launch ----------------
extern "C" void kernel_launch(void* const* d_in, const int* in_sizes, int n_in,
                              void* d_out, int out_size) {
    const float* x      = (const float*)d_in[0];
    const int*   edges  = (const int*)d_in[1];
    const int*   y      = (const int*)d_in[2];
    const float* Wrel1  = (const float*)d_in[3];
    const float* brel1  = (const float*)d_in[4];
    const float* Wroot1 = (const float*)d_in[5];
    const float* Wrel2  = (const float*)d_in[6];
    const float* brel2  = (const float*)d_in[7];
    const float* Wroot2 = (const float*)d_in[8];
    float* out = (float*)d_out;

    const int MT = (NN + 127) / 128;   // 157 M-tiles

    zero_cnt_kernel<<<(2 * NN + 255) / 256, 256>>>(out);
    fill_kernel<<<(4 * EE + 255) / 256, 256>>>(edges);

    prep_kernel<<<dim3(8, 8, 9), dim3(32, 8)>>>(Wrel1, brel1, Wroot1, Wrel2, brel2, Wroot2);

    gemm1_tc<<<dim3(MT, 2, 6), 256>>>(x);
    gather1_kernel<<<(2 * NN * 32) / 256, 256>>>();     // 5000 blocks

    gemm2_tc<<<dim3(MT, 2, 3), 256>>>();
    gather2_loss_kernel<<<NN / 8, 256>>>(y, out);       // 2500 blocks
}

// round 11
// speedup vs baseline: 1.3497x; 1.0400x over previous
#include <cuda_runtime.h>
#include <cuda_bf16.h>
#include <math.h>
#include <stdint.h>

#define NN 20000        // nodes per type
#define D  256          // feature dim
#define EE 320000       // edges per relation
#define ND (NN * D)
#define CAP 96          // bucket capacity per node per group (Poisson(32) + 11 sigma)

// ---------------- scratch (device globals: no allocation allowed) ----------------
__device__ __align__(16) float g_h0[ND];      // layer1 root+agg, type 0 (fp32)
__device__ __align__(16) float g_h1[ND];      // layer1 root+agg, type 1 (fp32)
__device__ __align__(16) float g_o2[ND];      // layer2 root part, type 0 (fp32)
__device__ __align__(16) __nv_bfloat16 g_xb[3 * ND];  // bf16 copy of x
__device__ __align__(16) __nv_bfloat16 g_hb0[ND];     // bf16 relu(h0)
__device__ __align__(16) __nv_bfloat16 g_hb1[ND];     // bf16 relu(h1)
__device__ __align__(16) __nv_bfloat16 g_yb0[ND];     // bf16 transformed features
__device__ __align__(16) __nv_bfloat16 g_yb1[ND];
__device__ __align__(16) __nv_bfloat16 g_yb2[ND];
__device__ __align__(16) __nv_bfloat16 g_yb3[ND];
__device__ __align__(16) __nv_bfloat16 g_WTb[9][D * D];  // bf16 pre-transposed weights [n][k]
__device__ float g_bc1[2 * D];
__device__ float g_bc2[D];

// Bucketed edge lists: group 0 = dst-type-0 (rel0 tag0, rel2 tag1) [reused by layer 2]
//                      group 1 = dst-type-1 (rel1 tag0, rel4 tag1)
__device__ int g_cnt[2][NN];
__device__ int g_rec[2][NN * CAP];

// pack two f32 into a bf16x2 word: low = a, high = b (PTX: cvt d, hi, lo)
__device__ __forceinline__ uint32_t bfpair(float a, float b) {
    uint32_t u;
    asm("cvt.rn.bf16x2.f32 %0, %1, %2;" : "=r"(u) : "f"(b), "f"(a));
    return u;
}

// ---------------- tiny kernels ----------------
// zero counters + the output scalar
__global__ void zero_cnt_kernel(float* o) {
    int i = blockIdx.x * blockDim.x + threadIdx.x;
    if (i < 2 * NN) ((int*)g_cnt)[i] = 0;
    if (i == 0) o[0] = 0.0f;
}

// x (fp32) -> g_xb (bf16), 4 floats per thread
__global__ void cvt_kernel(const float* __restrict__ x) {
    int i = blockIdx.x * blockDim.x + threadIdx.x;
    if (i < 3 * ND / 4) {
        float4 v = ((const float4*)x)[i];
        uint2 o;
        o.x = bfpair(v.x, v.y);
        o.y = bfpair(v.z, v.w);
        ((uint2*)g_xb)[i] = o;
    }
}

// segment s -> (rel k, group, tag):  s0:(0,0,0)  s1:(2,0,1)  s2:(1,1,0)  s3:(4,1,1)
__device__ __forceinline__ void seg_map(int s, int& k, int& grp, int& tag) {
    switch (s) {
        case 0:  k = 0; grp = 0; tag = 0; break;
        case 1:  k = 2; grp = 0; tag = 1; break;
        case 2:  k = 1; grp = 1; tag = 0; break;
        default: k = 4; grp = 1; tag = 1; break;
    }
}

// single pass: scatter edges into per-dst buckets
__global__ void fill_kernel(const int* __restrict__ edges) {
    int idx = blockIdx.x * blockDim.x + threadIdx.x;
    if (idx >= 4 * EE) return;
    int s = idx / EE, e = idx - s * EE;
    int k, grp, tag; seg_map(s, k, grp, tag);
    int src = edges[k * 2 * EE + e];
    int dst = edges[k * 2 * EE + EE + e];
    int pos = atomicAdd(&g_cnt[grp][dst], 1);
    if (pos < CAP)
        g_rec[grp][dst * CAP + pos] = (int)((unsigned)src | ((unsigned)tag << 31));
}

// Transpose (+ combine root pairs and biases) into g_WTb[9][n][k] (bf16).
__global__ void prep_kernel(const float* __restrict__ Wrel1, const float* __restrict__ brel1,
                            const float* __restrict__ Wroot1, const float* __restrict__ Wrel2,
                            const float* __restrict__ brel2, const float* __restrict__ Wroot2) {
    __shared__ float t[32][33];
    int j = blockIdx.z;
    const float* S0; const float* S1 = nullptr;
    switch (j) {
        case 0:  S0 = Wroot1;             S1 = Wroot1 + 2 * D * D; break;
        case 1:  S0 = Wroot1 + D * D;     S1 = Wroot1 + 4 * D * D; break;
        case 2:  S0 = Wrel1;              break;
        case 3:  S0 = Wrel1 + D * D;      break;
        case 4:  S0 = Wrel1 + 2 * D * D;  break;
        case 5:  S0 = Wrel1 + 4 * D * D;  break;
        case 6:  S0 = Wroot2;             S1 = Wroot2 + 2 * D * D; break;
        case 7:  S0 = Wrel2;              break;
        default: S0 = Wrel2 + 2 * D * D;  break;
    }
    int k0 = blockIdx.y * 32, n0 = blockIdx.x * 32;
    int tx = threadIdx.x, ty = threadIdx.y;     // 32 x 8
#pragma unroll
    for (int r = ty; r < 32; r += 8) {
        float v = S0[(size_t)(k0 + r) * D + n0 + tx];
        if (S1) v += S1[(size_t)(k0 + r) * D + n0 + tx];
        t[r][tx] = v;
    }
    __syncthreads();
    __nv_bfloat16* WT = g_WTb[j];
#pragma unroll
    for (int r = ty; r < 32; r += 8)
        WT[(size_t)(n0 + r) * D + k0 + tx] = __float2bfloat16_rn(t[tx][r]);

    if (blockIdx.x == 0 && blockIdx.y == 0 && j == 0) {
        int i = ty * 32 + tx;
        if (i < D) {
            g_bc1[i]     = brel1[i]         + brel1[2 * D + i];
            g_bc1[D + i] = brel1[D + i]     + brel1[4 * D + i];
            g_bc2[i]     = brel2[i]         + brel2[2 * D + i];
        }
    }
}

// ---------------- bf16 mma.sync GEMM, cp.async double-buffered ----------------
// C[M,256] = A[M,256] @ W (+bias). CTA tile 128x128, BK=32, 2-stage pipeline.
// SMEM rows: 16 data words (32 bf16) + 4 pad = stride 20 words (80B).
// Fragment LDS bank = (20*gid + tig) mod 32 -> all distinct, conflict-free.

#define TSTRIDE 20                       // words per SMEM row
#define TILEW   (128 * TSTRIDE)          // words per tile buffer

__device__ __forceinline__ void cp16(uint32_t dst, const void* src, int sz) {
    asm volatile("cp.async.cg.shared.global [%0], [%1], 16, %2;"
                 :: "r"(dst), "l"(src), "r"(sz) : "memory");
}
__device__ __forceinline__ void cp_commit() {
    asm volatile("cp.async.commit_group;" ::: "memory");
}

__device__ __forceinline__ void mma_bf16(float* c, const uint32_t* a, const uint32_t* b) {
    asm volatile(
        "mma.sync.aligned.m16n8k16.row.col.f32.bf16.bf16.f32 "
        "{%0,%1,%2,%3}, {%4,%5,%6,%7}, {%8,%9}, {%0,%1,%2,%3};"
        : "+f"(c[0]), "+f"(c[1]), "+f"(c[2]), "+f"(c[3])
        : "r"(a[0]), "r"(a[1]), "r"(a[2]), "r"(a[3]), "r"(b[0]), "r"(b[1]));
}

template <bool BF16OUT>
__device__ __forceinline__ void gemm_body(const __nv_bfloat16* __restrict__ A,
                                          const __nv_bfloat16* __restrict__ WT,
                                          const float* __restrict__ bias,
                                          float* __restrict__ Cf,
                                          __nv_bfloat16* __restrict__ Cb) {
    __shared__ __align__(16) uint32_t As[2][TILEW];
    __shared__ __align__(16) uint32_t Bs[2][TILEW];

    const int tid  = threadIdx.x;
    const int wid  = tid >> 5;
    const int lane = tid & 31;
    const int gid  = lane >> 2;
    const int tig  = lane & 3;
    const int m0 = blockIdx.x * 128;
    const int n0 = blockIdx.y * 128;
    const int wm = (wid & 3) * 32;
    const int wn = (wid >> 2) * 64;

    const int arow = tid >> 2;       // 0..63  (with i-offset covers 0..127)
    const int ac   = tid & 3;        // 16B chunk within row (4 chunks = 64B)
    uint32_t sA[2], sB[2];
    sA[0] = (uint32_t)__cvta_generic_to_shared(&As[0][0]);
    sA[1] = (uint32_t)__cvta_generic_to_shared(&As[1][0]);
    sB[0] = (uint32_t)__cvta_generic_to_shared(&Bs[0][0]);
    sB[1] = (uint32_t)__cvta_generic_to_shared(&Bs[1][0]);

    // stage tiles for k-chunk kc into buffer b
    auto stage = [&](int kc, int b) {
#pragma unroll
        for (int i = 0; i < 2; i++) {
            int row = arow + i * 64;
            int m = m0 + row;
            const void* src = A + (size_t)m * D + kc * 32 + ac * 8;
            cp16(sA[b] + (uint32_t)(row * TSTRIDE + ac * 4) * 4, src, m < NN ? 16 : 0);
        }
#pragma unroll
        for (int i = 0; i < 2; i++) {
            int row = arow + i * 64;
            const void* src = WT + (size_t)(n0 + row) * D + kc * 32 + ac * 8;
            cp16(sB[b] + (uint32_t)(row * TSTRIDE + ac * 4) * 4, src, 16);
        }
        cp_commit();
    };

    float acc[2][8][4];
#pragma unroll
    for (int mt = 0; mt < 2; mt++)
#pragma unroll
        for (int nt = 0; nt < 8; nt++)
#pragma unroll
            for (int q = 0; q < 4; q++) acc[mt][nt][q] = 0.0f;

    stage(0, 0);

    for (int kc = 0; kc < 8; kc++) {
        const int buf = kc & 1;
        if (kc < 7) {
            stage(kc + 1, buf ^ 1);
            asm volatile("cp.async.wait_group 1;" ::: "memory");
        } else {
            asm volatile("cp.async.wait_group 0;" ::: "memory");
        }
        __syncthreads();

        const uint32_t* __restrict__ pa = As[buf];
        const uint32_t* __restrict__ pb = Bs[buf];
#pragma unroll
        for (int ks = 0; ks < 2; ks++) {
            const int kw0 = ks * 8;
            uint32_t af[2][4], bf[8][2];
#pragma unroll
            for (int mt = 0; mt < 2; mt++) {
                int r = wm + mt * 16 + gid;
                af[mt][0] = pa[r * TSTRIDE + kw0 + tig];
                af[mt][1] = pa[(r + 8) * TSTRIDE + kw0 + tig];
                af[mt][2] = pa[r * TSTRIDE + kw0 + tig + 4];
                af[mt][3] = pa[(r + 8) * TSTRIDE + kw0 + tig + 4];
            }
#pragma unroll
            for (int nt = 0; nt < 8; nt++) {
                int c = wn + nt * 8 + gid;
                bf[nt][0] = pb[c * TSTRIDE + kw0 + tig];
                bf[nt][1] = pb[c * TSTRIDE + kw0 + tig + 4];
            }
#pragma unroll
            for (int mt = 0; mt < 2; mt++)
#pragma unroll
                for (int nt = 0; nt < 8; nt++)
                    mma_bf16(acc[mt][nt], af[mt], bf[nt]);
        }
        __syncthreads();
    }

#pragma unroll
    for (int mt = 0; mt < 2; mt++) {
        int m_lo = m0 + wm + mt * 16 + gid;
        int m_hi = m_lo + 8;
#pragma unroll
        for (int nt = 0; nt < 8; nt++) {
            int n = n0 + wn + nt * 8 + tig * 2;
            if (BF16OUT) {
                if (m_lo < NN)
                    *(uint32_t*)(Cb + (size_t)m_lo * D + n) =
                        bfpair(acc[mt][nt][0], acc[mt][nt][1]);
                if (m_hi < NN)
                    *(uint32_t*)(Cb + (size_t)m_hi * D + n) =
                        bfpair(acc[mt][nt][2], acc[mt][nt][3]);
            } else {
                float b0 = bias ? bias[n] : 0.f;
                float b1 = bias ? bias[n + 1] : 0.f;
                if (m_lo < NN)
                    *(float2*)(Cf + (size_t)m_lo * D + n) =
                        make_float2(acc[mt][nt][0] + b0, acc[mt][nt][1] + b1);
                if (m_hi < NN)
                    *(float2*)(Cf + (size_t)m_hi * D + n) =
                        make_float2(acc[mt][nt][2] + b0, acc[mt][nt][3] + b1);
            }
        }
    }
}

// Layer 1 (6 jobs): roots (fp32+bias) + 4 rel GEMMs (bf16 out). A = g_xb.
__global__ __launch_bounds__(256, 2) void gemm1_tc() {
    switch (blockIdx.z) {
        case 0:  gemm_body<false>(g_xb,          g_WTb[0], g_bc1,     g_h0, nullptr); break;
        case 1:  gemm_body<false>(g_xb + ND,     g_WTb[1], g_bc1 + D, g_h1, nullptr); break;
        case 2:  gemm_body<true >(g_xb,          g_WTb[2], nullptr, nullptr, g_yb0); break;
        case 3:  gemm_body<true >(g_xb,          g_WTb[3], nullptr, nullptr, g_yb2); break;
        case 4:  gemm_body<true >(g_xb + ND,     g_WTb[4], nullptr, nullptr, g_yb1); break;
        default: gemm_body<true >(g_xb + 2 * ND, g_WTb[5], nullptr, nullptr, g_yb3); break;
    }
}

// Layer 2 (3 jobs; only dst type 0 feeds the loss). A = relu'd bf16 h from gather1.
__global__ __launch_bounds__(256, 2) void gemm2_tc() {
    switch (blockIdx.z) {
        case 0:  gemm_body<false>(g_hb0, g_WTb[6], g_bc2, g_o2, nullptr); break;
        case 1:  gemm_body<true >(g_hb0, g_WTb[7], nullptr, nullptr, g_yb0); break;
        default: gemm_body<true >(g_hb1, g_WTb[8], nullptr, nullptr, g_yb1); break;
    }
}

// ---------------- bucket gather: one warp per dst node ----------------
__device__ __forceinline__ void accum_row(float* acc, const __nv_bfloat16* __restrict__ y0,
                                          const __nv_bfloat16* __restrict__ y1,
                                          int rec, int lane) {
    const __nv_bfloat16* yb = (rec < 0) ? y1 : y0;
    int src = rec & 0x7fffffff;
    uint4 v = *(const uint4*)(yb + (size_t)src * D + lane * 8);
    const __nv_bfloat162* p = (const __nv_bfloat162*)&v;
    float2 f0 = __bfloat1622float2(p[0]);
    float2 f1 = __bfloat1622float2(p[1]);
    float2 f2 = __bfloat1622float2(p[2]);
    float2 f3 = __bfloat1622float2(p[3]);
    acc[0] += f0.x; acc[1] += f0.y; acc[2] += f1.x; acc[3] += f1.y;
    acc[4] += f2.x; acc[5] += f2.y; acc[6] += f3.x; acc[7] += f3.y;
}

// accumulate the bucket of (grp, node) into acc[8] (lane owns cols lane*8..lane*8+7)
__device__ __forceinline__ void gather_accum(int grp, int node,
                                             const __nv_bfloat16* __restrict__ y0,
                                             const __nv_bfloat16* __restrict__ y1,
                                             float* acc, int lane) {
    const int* __restrict__ recs = g_rec[grp] + node * CAP;
    int cnt = g_cnt[grp][node];
    if (cnt > CAP) cnt = CAP;

    for (int base = 0; base < cnt; base += 32) {
        int m = cnt - base;
        if (m > 32) m = 32;
        int rec = 0;
        if (lane < m) rec = recs[base + lane];
        int j = 0;
        for (; j + 4 <= m; j += 4) {
            int r0 = __shfl_sync(0xFFFFFFFFu, rec, j);
            int r1 = __shfl_sync(0xFFFFFFFFu, rec, j + 1);
            int r2 = __shfl_sync(0xFFFFFFFFu, rec, j + 2);
            int r3 = __shfl_sync(0xFFFFFFFFu, rec, j + 3);
            accum_row(acc, y0, y1, r0, lane);
            accum_row(acc, y0, y1, r1, lane);
            accum_row(acc, y0, y1, r2, lane);
            accum_row(acc, y0, y1, r3, lane);
        }
        for (; j < m; j++) {
            int r = __shfl_sync(0xFFFFFFFFu, rec, j);
            accum_row(acc, y0, y1, r, lane);
        }
    }
}

// layer-1 gather: h = root + agg; write bf16 relu(h) for layer 2
__global__ void gather1_kernel() {
    int gw   = (blockIdx.x * blockDim.x + threadIdx.x) >> 5;   // 0..39999
    int lane = threadIdx.x & 31;
    int grp  = gw >= NN;
    int node = gw - grp * NN;

    float acc[8] = {0.f, 0.f, 0.f, 0.f, 0.f, 0.f, 0.f, 0.f};
    if (grp == 0) gather_accum(0, node, g_yb0, g_yb1, acc, lane);
    else          gather_accum(1, node, g_yb2, g_yb3, acc, lane);

    const float* rootp = (grp == 0 ? g_h0 : g_h1) + (size_t)node * D + lane * 8;
    float4 a = *(const float4*)rootp;
    float4 b = *(const float4*)(rootp + 4);
    uint4 w;
    w.x = bfpair(fmaxf(a.x + acc[0], 0.f), fmaxf(a.y + acc[1], 0.f));
    w.y = bfpair(fmaxf(a.z + acc[2], 0.f), fmaxf(a.w + acc[3], 0.f));
    w.z = bfpair(fmaxf(b.x + acc[4], 0.f), fmaxf(b.y + acc[5], 0.f));
    w.w = bfpair(fmaxf(b.z + acc[6], 0.f), fmaxf(b.w + acc[7], 0.f));
    __nv_bfloat16* hb = grp == 0 ? g_hb0 : g_hb1;
    *(uint4*)(hb + (size_t)node * D + lane * 8) = w;
}

// ---------------- fused layer-2 gather + loss ----------------
__global__ void gather2_loss_kernel(const int* __restrict__ y, float* __restrict__ out) {
    int gw   = (blockIdx.x * blockDim.x + threadIdx.x) >> 5;   // 0..19999
    int lane = threadIdx.x & 31;

    float acc[8] = {0.f, 0.f, 0.f, 0.f, 0.f, 0.f, 0.f, 0.f};
    gather_accum(0, gw, g_yb0, g_yb1, acc, lane);

    const float* rp = g_o2 + (size_t)gw * D + lane * 8;
    float4 a = *(const float4*)rp;
    float4 b = *(const float4*)(rp + 4);
    float v[8];
    v[0] = a.x + acc[0]; v[1] = a.y + acc[1]; v[2] = a.z + acc[2]; v[3] = a.w + acc[3];
    v[4] = b.x + acc[4]; v[5] = b.y + acc[5]; v[6] = b.z + acc[6]; v[7] = b.w + acc[7];

    float m = v[0];
#pragma unroll
    for (int i = 1; i < 8; i++) m = fmaxf(m, v[i]);
#pragma unroll
    for (int o = 16; o; o >>= 1) m = fmaxf(m, __shfl_xor_sync(0xFFFFFFFFu, m, o));

    float s = 0.0f;
#pragma unroll
    for (int i = 0; i < 8; i++) s += expf(v[i] - m);
#pragma unroll
    for (int o = 16; o; o >>= 1) s += __shfl_xor_sync(0xFFFFFFFFu, s, o);

    int yy = y[gw];
    float tv = v[0];
#pragma unroll
    for (int j = 1; j < 8; j++) tv = ((yy & 7) == j) ? v[j] : tv;
    float target = __shfl_sync(0xFFFFFFFFu, tv, yy >> 3);

    float nll = (m + logf(s)) - target;

    __shared__ float partial[8];
    if (lane == 0) partial[threadIdx.x >> 5] = nll;
    __syncthreads();
    if (threadIdx.x == 0) {
        float t = 0.0f;
#pragma unroll
        for (int i = 0; i < 8; i++) t += partial[i];
        atomicAdd(out, t * (1.0f / (float)NN));
    }
}

// ---------------- launch ----------------
extern "C" void kernel_launch(void* const* d_in, const int* in_sizes, int n_in,
                              void* d_out, int out_size) {
    const float* x      = (const float*)d_in[0];
    const int*   edges  = (const int*)d_in[1];
    const int*   y      = (const int*)d_in[2];
    const float* Wrel1  = (const float*)d_in[3];
    const float* brel1  = (const float*)d_in[4];
    const float* Wroot1 = (const float*)d_in[5];
    const float* Wrel2  = (const float*)d_in[6];
    const float* brel2  = (const float*)d_in[7];
    const float* Wroot2 = (const float*)d_in[8];
    float* out = (float*)d_out;

    const int MT = (NN + 127) / 128;   // 157 M-tiles

    zero_cnt_kernel<<<(2 * NN + 255) / 256, 256>>>(out);
    fill_kernel<<<(4 * EE + 255) / 256, 256>>>(edges);
    cvt_kernel<<<(3 * ND / 4 + 255) / 256, 256>>>(x);

    prep_kernel<<<dim3(8, 8, 9), dim3(32, 8)>>>(Wrel1, brel1, Wroot1, Wrel2, brel2, Wroot2);

    gemm1_tc<<<dim3(MT, 2, 6), 256>>>();
    gather1_kernel<<<(2 * NN * 32) / 256, 256>>>();     // 5000 blocks

    gemm2_tc<<<dim3(MT, 2, 3), 256>>>();
    gather2_loss_kernel<<<NN / 8, 256>>>(y, out);       // 2500 blocks
}

// round 12
// speedup vs baseline: 1.4685x; 1.0880x over previous
#include <cuda_runtime.h>
#include <cuda_bf16.h>
#include <math.h>
#include <stdint.h>

#define NN 20000        // nodes per type
#define D  256          // feature dim
#define EE 320000       // edges per relation
#define ND (NN * D)
#define CAP 96          // bucket capacity per node per group (Poisson(32) + 11 sigma)

// ---------------- scratch (device globals: no allocation allowed) ----------------
__device__ __align__(16) float g_h0[ND];      // layer1 root+agg, type 0 (fp32)
__device__ __align__(16) float g_h1[ND];      // layer1 root+agg, type 1 (fp32)
__device__ __align__(16) float g_o2[ND];      // layer2 root part, type 0 (fp32)
__device__ __align__(16) __nv_bfloat16 g_xb[3 * ND];  // bf16 copy of x
__device__ __align__(16) __nv_bfloat16 g_hb0[ND];     // bf16 relu(h0)
__device__ __align__(16) __nv_bfloat16 g_hb1[ND];     // bf16 relu(h1)
__device__ __align__(16) __nv_bfloat16 g_yb0[ND];     // bf16 transformed features
__device__ __align__(16) __nv_bfloat16 g_yb1[ND];
__device__ __align__(16) __nv_bfloat16 g_yb2[ND];
__device__ __align__(16) __nv_bfloat16 g_yb3[ND];
__device__ __align__(16) __nv_bfloat16 g_WTb[9][D * D];  // bf16 pre-transposed weights [n][k]
__device__ float g_bc1[2 * D];
__device__ float g_bc2[D];

// Bucketed edge lists: group 0 = dst-type-0 (rel0 tag0, rel2 tag1) [reused by layer 2]
//                      group 1 = dst-type-1 (rel1 tag0, rel4 tag1)
__device__ int g_cnt[2][NN];
__device__ int g_rec[2][NN * CAP];

// pack two f32 into a bf16x2 word: low = a, high = b (PTX: cvt d, hi, lo)
__device__ __forceinline__ uint32_t bfpair(float a, float b) {
    uint32_t u;
    asm("cvt.rn.bf16x2.f32 %0, %1, %2;" : "=r"(u) : "f"(b), "f"(a));
    return u;
}

// ---------------- tiny kernels ----------------
__global__ void zero_cnt_kernel(float* o) {
    int i = blockIdx.x * blockDim.x + threadIdx.x;
    if (i < 2 * NN) ((int*)g_cnt)[i] = 0;
    if (i == 0) o[0] = 0.0f;
}

// x (fp32) -> g_xb (bf16), 4 floats per thread
__global__ void cvt_kernel(const float* __restrict__ x) {
    int i = blockIdx.x * blockDim.x + threadIdx.x;
    if (i < 3 * ND / 4) {
        float4 v = ((const float4*)x)[i];
        uint2 o;
        o.x = bfpair(v.x, v.y);
        o.y = bfpair(v.z, v.w);
        ((uint2*)g_xb)[i] = o;
    }
}

// segment s -> (rel k, group, tag):  s0:(0,0,0)  s1:(2,0,1)  s2:(1,1,0)  s3:(4,1,1)
__device__ __forceinline__ void seg_map(int s, int& k, int& grp, int& tag) {
    switch (s) {
        case 0:  k = 0; grp = 0; tag = 0; break;
        case 1:  k = 2; grp = 0; tag = 1; break;
        case 2:  k = 1; grp = 1; tag = 0; break;
        default: k = 4; grp = 1; tag = 1; break;
    }
}

// single pass: scatter edges into per-dst buckets
__global__ void fill_kernel(const int* __restrict__ edges) {
    int idx = blockIdx.x * blockDim.x + threadIdx.x;
    if (idx >= 4 * EE) return;
    int s = idx / EE, e = idx - s * EE;
    int k, grp, tag; seg_map(s, k, grp, tag);
    int src = edges[k * 2 * EE + e];
    int dst = edges[k * 2 * EE + EE + e];
    int pos = atomicAdd(&g_cnt[grp][dst], 1);
    if (pos < CAP)
        g_rec[grp][dst * CAP + pos] = (int)((unsigned)src | ((unsigned)tag << 31));
}

// Transpose (+ combine root pairs and biases) into g_WTb[9][n][k] (bf16).
__global__ void prep_kernel(const float* __restrict__ Wrel1, const float* __restrict__ brel1,
                            const float* __restrict__ Wroot1, const float* __restrict__ Wrel2,
                            const float* __restrict__ brel2, const float* __restrict__ Wroot2) {
    __shared__ float t[32][33];
    int j = blockIdx.z;
    const float* S0; const float* S1 = nullptr;
    switch (j) {
        case 0:  S0 = Wroot1;             S1 = Wroot1 + 2 * D * D; break;
        case 1:  S0 = Wroot1 + D * D;     S1 = Wroot1 + 4 * D * D; break;
        case 2:  S0 = Wrel1;              break;
        case 3:  S0 = Wrel1 + D * D;      break;
        case 4:  S0 = Wrel1 + 2 * D * D;  break;
        case 5:  S0 = Wrel1 + 4 * D * D;  break;
        case 6:  S0 = Wroot2;             S1 = Wroot2 + 2 * D * D; break;
        case 7:  S0 = Wrel2;              break;
        default: S0 = Wrel2 + 2 * D * D;  break;
    }
    int k0 = blockIdx.y * 32, n0 = blockIdx.x * 32;
    int tx = threadIdx.x, ty = threadIdx.y;     // 32 x 8
#pragma unroll
    for (int r = ty; r < 32; r += 8) {
        float v = S0[(size_t)(k0 + r) * D + n0 + tx];
        if (S1) v += S1[(size_t)(k0 + r) * D + n0 + tx];
        t[r][tx] = v;
    }
    __syncthreads();
    __nv_bfloat16* WT = g_WTb[j];
#pragma unroll
    for (int r = ty; r < 32; r += 8)
        WT[(size_t)(n0 + r) * D + k0 + tx] = __float2bfloat16_rn(t[tx][r]);

    if (blockIdx.x == 0 && blockIdx.y == 0 && j == 0) {
        int i = ty * 32 + tx;
        if (i < D) {
            g_bc1[i]     = brel1[i]         + brel1[2 * D + i];
            g_bc1[D + i] = brel1[D + i]     + brel1[4 * D + i];
            g_bc2[i]     = brel2[i]         + brel2[2 * D + i];
        }
    }
}

// ---------------- bf16 mma.sync GEMM, 4-stage cp.async + ldmatrix ----------------
// C[M,256] = A[M,256] @ W (+bias). CTA tile 128x128, BK=32, 4-stage ring.
// SMEM rows: 16 data words (32 bf16) + 4 pad = stride 20 words (80B).
// 8 rows under stride-20 hit banks {0,20,8,28,16,4,24,12}x4 = all 32 -> ldmatrix conflict-free.

#define TSTRIDE 20                        // words per SMEM row
#define TILEB   (128 * TSTRIDE * 4)       // bytes per tile buffer (10240)
#define NSTAGE  4
#define SMEM_GEMM (2 * NSTAGE * TILEB)    // 81920 bytes

__device__ __forceinline__ void cp16(uint32_t dst, const void* src, int sz) {
    asm volatile("cp.async.cg.shared.global [%0], [%1], 16, %2;"
                 :: "r"(dst), "l"(src), "r"(sz) : "memory");
}
__device__ __forceinline__ void cp_commit() {
    asm volatile("cp.async.commit_group;" ::: "memory");
}
__device__ __forceinline__ void ldm4(uint32_t& r0, uint32_t& r1, uint32_t& r2, uint32_t& r3,
                                     uint32_t addr) {
    asm volatile("ldmatrix.sync.aligned.m8n8.x4.shared.b16 {%0,%1,%2,%3}, [%4];"
                 : "=r"(r0), "=r"(r1), "=r"(r2), "=r"(r3) : "r"(addr));
}

__device__ __forceinline__ void mma_bf16(float* c, const uint32_t* a, const uint32_t* b) {
    asm volatile(
        "mma.sync.aligned.m16n8k16.row.col.f32.bf16.bf16.f32 "
        "{%0,%1,%2,%3}, {%4,%5,%6,%7}, {%8,%9}, {%0,%1,%2,%3};"
        : "+f"(c[0]), "+f"(c[1]), "+f"(c[2]), "+f"(c[3])
        : "r"(a[0]), "r"(a[1]), "r"(a[2]), "r"(a[3]), "r"(b[0]), "r"(b[1]));
}

template <bool BF16OUT>
__device__ __forceinline__ void gemm_body(const __nv_bfloat16* __restrict__ A,
                                          const __nv_bfloat16* __restrict__ WT,
                                          const float* __restrict__ bias,
                                          float* __restrict__ Cf,
                                          __nv_bfloat16* __restrict__ Cb) {
    extern __shared__ __align__(16) uint32_t smem[];
    const uint32_t sbase = (uint32_t)__cvta_generic_to_shared(smem);
    // A stage s at sbase + s*TILEB; B stage s at sbase + 4*TILEB + s*TILEB

    const int tid  = threadIdx.x;
    const int wid  = tid >> 5;
    const int lane = tid & 31;
    const int gid  = lane >> 2;
    const int tig  = lane & 3;
    const int m0 = blockIdx.x * 128;
    const int n0 = blockIdx.y * 128;
    const int wm = (wid & 3) * 32;
    const int wn = (wid >> 2) * 64;

    const int arow = tid >> 2;       // staging: 0..63 (+64 with i)
    const int ac   = tid & 3;        // 16B chunk within 64B row

    // ldmatrix per-lane byte offsets (within a stage buffer), k-half 0
    // A (mt): rows wm+mt*16 + ((lane>>3)&1)*8 + (lane&7), +4 words if lane>=16
    uint32_t aoff[2];
#pragma unroll
    for (int mt = 0; mt < 2; mt++) {
        int row = wm + mt * 16 + ((lane >> 3) & 1) * 8 + (lane & 7);
        aoff[mt] = (uint32_t)(row * TSTRIDE + (lane >> 4) * 4) * 4;
    }
    // B (nt-pair p): rows wn+p*16 + ((lane>>4)?8:0) + (lane&7), +4 words if (lane>>3)&1
    uint32_t boff[4];
#pragma unroll
    for (int p = 0; p < 4; p++) {
        int row = wn + p * 16 + ((lane >> 4) & 1) * 8 + (lane & 7);
        boff[p] = (uint32_t)(row * TSTRIDE + ((lane >> 3) & 1) * 4) * 4;
    }

    // stage tiles for k-chunk kc into ring slot b
    auto stage = [&](int kc, int b) {
        uint32_t sa = sbase + (uint32_t)b * TILEB;
        uint32_t sb = sbase + (uint32_t)(NSTAGE + b) * TILEB;
#pragma unroll
        for (int i = 0; i < 2; i++) {
            int row = arow + i * 64;
            int m = m0 + row;
            const void* src = A + (size_t)m * D + kc * 32 + ac * 8;
            cp16(sa + (uint32_t)(row * 80 + ac * 16), src, m < NN ? 16 : 0);
        }
#pragma unroll
        for (int i = 0; i < 2; i++) {
            int row = arow + i * 64;
            const void* src = WT + (size_t)(n0 + row) * D + kc * 32 + ac * 8;
            cp16(sb + (uint32_t)(row * 80 + ac * 16), src, 16);
        }
        cp_commit();
    };

    float acc[2][8][4];
#pragma unroll
    for (int mt = 0; mt < 2; mt++)
#pragma unroll
        for (int nt = 0; nt < 8; nt++)
#pragma unroll
            for (int q = 0; q < 4; q++) acc[mt][nt][q] = 0.0f;

    stage(0, 0);
    stage(1, 1);
    stage(2, 2);

    for (int kc = 0; kc < 8; kc++) {
        const int buf = kc & 3;
        if (kc < 6)      asm volatile("cp.async.wait_group 2;" ::: "memory");
        else if (kc == 6) asm volatile("cp.async.wait_group 1;" ::: "memory");
        else             asm volatile("cp.async.wait_group 0;" ::: "memory");
        __syncthreads();

        const uint32_t pa = sbase + (uint32_t)buf * TILEB;
        const uint32_t pb = sbase + (uint32_t)(NSTAGE + buf) * TILEB;
#pragma unroll
        for (int ks = 0; ks < 2; ks++) {
            const uint32_t kb = ks * 32;     // k-half byte offset (8 words)
            uint32_t af[2][4], bf[8][2];
#pragma unroll
            for (int mt = 0; mt < 2; mt++)
                ldm4(af[mt][0], af[mt][1], af[mt][2], af[mt][3], pa + aoff[mt] + kb);
#pragma unroll
            for (int p = 0; p < 4; p++)
                ldm4(bf[2 * p][0], bf[2 * p][1], bf[2 * p + 1][0], bf[2 * p + 1][1],
                     pb + boff[p] + kb);
#pragma unroll
            for (int mt = 0; mt < 2; mt++)
#pragma unroll
                for (int nt = 0; nt < 8; nt++)
                    mma_bf16(acc[mt][nt], af[mt], bf[nt]);
        }
        int nk = kc + 3;
        if (nk < 8) stage(nk, nk & 3);
    }

#pragma unroll
    for (int mt = 0; mt < 2; mt++) {
        int m_lo = m0 + wm + mt * 16 + gid;
        int m_hi = m_lo + 8;
#pragma unroll
        for (int nt = 0; nt < 8; nt++) {
            int n = n0 + wn + nt * 8 + tig * 2;
            if (BF16OUT) {
                if (m_lo < NN)
                    *(uint32_t*)(Cb + (size_t)m_lo * D + n) =
                        bfpair(acc[mt][nt][0], acc[mt][nt][1]);
                if (m_hi < NN)
                    *(uint32_t*)(Cb + (size_t)m_hi * D + n) =
                        bfpair(acc[mt][nt][2], acc[mt][nt][3]);
            } else {
                float b0 = bias ? bias[n] : 0.f;
                float b1 = bias ? bias[n + 1] : 0.f;
                if (m_lo < NN)
                    *(float2*)(Cf + (size_t)m_lo * D + n) =
                        make_float2(acc[mt][nt][0] + b0, acc[mt][nt][1] + b1);
                if (m_hi < NN)
                    *(float2*)(Cf + (size_t)m_hi * D + n) =
                        make_float2(acc[mt][nt][2] + b0, acc[mt][nt][3] + b1);
            }
        }
    }
}

// Layer 1 (6 jobs): roots (fp32+bias) + 4 rel GEMMs (bf16 out). A = g_xb.
__global__ __launch_bounds__(256, 2) void gemm1_tc() {
    switch (blockIdx.z) {
        case 0:  gemm_body<false>(g_xb,          g_WTb[0], g_bc1,     g_h0, nullptr); break;
        case 1:  gemm_body<false>(g_xb + ND,     g_WTb[1], g_bc1 + D, g_h1, nullptr); break;
        case 2:  gemm_body<true >(g_xb,          g_WTb[2], nullptr, nullptr, g_yb0); break;
        case 3:  gemm_body<true >(g_xb,          g_WTb[3], nullptr, nullptr, g_yb2); break;
        case 4:  gemm_body<true >(g_xb + ND,     g_WTb[4], nullptr, nullptr, g_yb1); break;
        default: gemm_body<true >(g_xb + 2 * ND, g_WTb[5], nullptr, nullptr, g_yb3); break;
    }
}

// Layer 2 (3 jobs; only dst type 0 feeds the loss). A = relu'd bf16 h from gather1.
__global__ __launch_bounds__(256, 2) void gemm2_tc() {
    switch (blockIdx.z) {
        case 0:  gemm_body<false>(g_hb0, g_WTb[6], g_bc2, g_o2, nullptr); break;
        case 1:  gemm_body<true >(g_hb0, g_WTb[7], nullptr, nullptr, g_yb0); break;
        default: gemm_body<true >(g_hb1, g_WTb[8], nullptr, nullptr, g_yb1); break;
    }
}

// ---------------- bucket gather: one warp per dst node ----------------
__device__ __forceinline__ void accum_row(float* acc, const __nv_bfloat16* __restrict__ y0,
                                          const __nv_bfloat16* __restrict__ y1,
                                          int rec, int lane) {
    const __nv_bfloat16* yb = (rec < 0) ? y1 : y0;
    int src = rec & 0x7fffffff;
    uint4 v = *(const uint4*)(yb + (size_t)src * D + lane * 8);
    const __nv_bfloat162* p = (const __nv_bfloat162*)&v;
    float2 f0 = __bfloat1622float2(p[0]);
    float2 f1 = __bfloat1622float2(p[1]);
    float2 f2 = __bfloat1622float2(p[2]);
    float2 f3 = __bfloat1622float2(p[3]);
    acc[0] += f0.x; acc[1] += f0.y; acc[2] += f1.x; acc[3] += f1.y;
    acc[4] += f2.x; acc[5] += f2.y; acc[6] += f3.x; acc[7] += f3.y;
}

__device__ __forceinline__ void gather_accum(int grp, int node,
                                             const __nv_bfloat16* __restrict__ y0,
                                             const __nv_bfloat16* __restrict__ y1,
                                             float* acc, int lane) {
    const int* __restrict__ recs = g_rec[grp] + node * CAP;
    int cnt = g_cnt[grp][node];
    if (cnt > CAP) cnt = CAP;

    for (int base = 0; base < cnt; base += 32) {
        int m = cnt - base;
        if (m > 32) m = 32;
        int rec = 0;
        if (lane < m) rec = recs[base + lane];
        int j = 0;
        for (; j + 4 <= m; j += 4) {
            int r0 = __shfl_sync(0xFFFFFFFFu, rec, j);
            int r1 = __shfl_sync(0xFFFFFFFFu, rec, j + 1);
            int r2 = __shfl_sync(0xFFFFFFFFu, rec, j + 2);
            int r3 = __shfl_sync(0xFFFFFFFFu, rec, j + 3);
            accum_row(acc, y0, y1, r0, lane);
            accum_row(acc, y0, y1, r1, lane);
            accum_row(acc, y0, y1, r2, lane);
            accum_row(acc, y0, y1, r3, lane);
        }
        for (; j < m; j++) {
            int r = __shfl_sync(0xFFFFFFFFu, rec, j);
            accum_row(acc, y0, y1, r, lane);
        }
    }
}

// layer-1 gather: h = root + agg; write bf16 relu(h) for layer 2
__global__ void gather1_kernel() {
    int gw   = (blockIdx.x * blockDim.x + threadIdx.x) >> 5;   // 0..39999
    int lane = threadIdx.x & 31;
    int grp  = gw >= NN;
    int node = gw - grp * NN;

    float acc[8] = {0.f, 0.f, 0.f, 0.f, 0.f, 0.f, 0.f, 0.f};
    if (grp == 0) gather_accum(0, node, g_yb0, g_yb1, acc, lane);
    else          gather_accum(1, node, g_yb2, g_yb3, acc, lane);

    const float* rootp = (grp == 0 ? g_h0 : g_h1) + (size_t)node * D + lane * 8;
    float4 a = *(const float4*)rootp;
    float4 b = *(const float4*)(rootp + 4);
    uint4 w;
    w.x = bfpair(fmaxf(a.x + acc[0], 0.f), fmaxf(a.y + acc[1], 0.f));
    w.y = bfpair(fmaxf(a.z + acc[2], 0.f), fmaxf(a.w + acc[3], 0.f));
    w.z = bfpair(fmaxf(b.x + acc[4], 0.f), fmaxf(b.y + acc[5], 0.f));
    w.w = bfpair(fmaxf(b.z + acc[6], 0.f), fmaxf(b.w + acc[7], 0.f));
    __nv_bfloat16* hb = grp == 0 ? g_hb0 : g_hb1;
    *(uint4*)(hb + (size_t)node * D + lane * 8) = w;
}

// ---------------- fused layer-2 gather + loss ----------------
__global__ void gather2_loss_kernel(const int* __restrict__ y, float* __restrict__ out) {
    int gw   = (blockIdx.x * blockDim.x + threadIdx.x) >> 5;   // 0..19999
    int lane = threadIdx.x & 31;

    float acc[8] = {0.f, 0.f, 0.f, 0.f, 0.f, 0.f, 0.f, 0.f};
    gather_accum(0, gw, g_yb0, g_yb1, acc, lane);

    const float* rp = g_o2 + (size_t)gw * D + lane * 8;
    float4 a = *(const float4*)rp;
    float4 b = *(const float4*)(rp + 4);
    float v[8];
    v[0] = a.x + acc[0]; v[1] = a.y + acc[1]; v[2] = a.z + acc[2]; v[3] = a.w + acc[3];
    v[4] = b.x + acc[4]; v[5] = b.y + acc[5]; v[6] = b.z + acc[6]; v[7] = b.w + acc[7];

    float m = v[0];
#pragma unroll
    for (int i = 1; i < 8; i++) m = fmaxf(m, v[i]);
#pragma unroll
    for (int o = 16; o; o >>= 1) m = fmaxf(m, __shfl_xor_sync(0xFFFFFFFFu, m, o));

    float s = 0.0f;
#pragma unroll
    for (int i = 0; i < 8; i++) s += expf(v[i] - m);
#pragma unroll
    for (int o = 16; o; o >>= 1) s += __shfl_xor_sync(0xFFFFFFFFu, s, o);

    int yy = y[gw];
    float tv = v[0];
#pragma unroll
    for (int j = 1; j < 8; j++) tv = ((yy & 7) == j) ? v[j] : tv;
    float target = __shfl_sync(0xFFFFFFFFu, tv, yy >> 3);

    float nll = (m + logf(s)) - target;

    __shared__ float partial[8];
    if (lane == 0) partial[threadIdx.x >> 5] = nll;
    __syncthreads();
    if (threadIdx.x == 0) {
        float t = 0.0f;
#pragma unroll
        for (int i = 0; i < 8; i++) t += partial[i];
        atomicAdd(out, t * (1.0f / (float)NN));
    }
}

// ---------------- launch ----------------
extern "C" void kernel_launch(void* const* d_in, const int* in_sizes, int n_in,
                              void* d_out, int out_size) {
    const float* x      = (const float*)d_in[0];
    const int*   edges  = (const int*)d_in[1];
    const int*   y      = (const int*)d_in[2];
    const float* Wrel1  = (const float*)d_in[3];
    const float* brel1  = (const float*)d_in[4];
    const float* Wroot1 = (const float*)d_in[5];
    const float* Wrel2  = (const float*)d_in[6];
    const float* brel2  = (const float*)d_in[7];
    const float* Wroot2 = (const float*)d_in[8];
    float* out = (float*)d_out;

    cudaFuncSetAttribute(gemm1_tc, cudaFuncAttributeMaxDynamicSharedMemorySize, SMEM_GEMM);
    cudaFuncSetAttribute(gemm2_tc, cudaFuncAttributeMaxDynamicSharedMemorySize, SMEM_GEMM);

    const int MT = (NN + 127) / 128;   // 157 M-tiles

    zero_cnt_kernel<<<(2 * NN + 255) / 256, 256>>>(out);
    fill_kernel<<<(4 * EE + 255) / 256, 256>>>(edges);
    cvt_kernel<<<(3 * ND / 4 + 255) / 256, 256>>>(x);

    prep_kernel<<<dim3(8, 8, 9), dim3(32, 8)>>>(Wrel1, brel1, Wroot1, Wrel2, brel2, Wroot2);

    gemm1_tc<<<dim3(MT, 2, 6), 256, SMEM_GEMM>>>();
    gather1_kernel<<<(2 * NN * 32) / 256, 256>>>();     // 5000 blocks

    gemm2_tc<<<dim3(MT, 2, 3), 256, SMEM_GEMM>>>();
    gather2_loss_kernel<<<NN / 8, 256>>>(y, out);       // 2500 blocks
}

// round 13
// speedup vs baseline: 1.5971x; 1.0876x over previous
#include <cuda_runtime.h>
#include <cuda_bf16.h>
#include <math.h>
#include <stdint.h>

#define NN 20000        // nodes per type
#define D  256          // feature dim
#define EE 320000       // edges per relation
#define ND (NN * D)
#define CAP 96          // bucket capacity per node per group (Poisson(32) + 11 sigma)

// ---------------- scratch (device globals: no allocation allowed) ----------------
__device__ __align__(16) float g_h0[ND];      // layer1 root+agg, type 0 (fp32)
__device__ __align__(16) float g_h1[ND];      // layer1 root+agg, type 1 (fp32)
__device__ __align__(16) float g_o2[ND];      // layer2 root part, type 0 (fp32)
__device__ __align__(16) __nv_bfloat16 g_xb[3 * ND];  // bf16 copy of x
__device__ __align__(16) __nv_bfloat16 g_hb0[ND];     // bf16 relu(h0)
__device__ __align__(16) __nv_bfloat16 g_hb1[ND];     // bf16 relu(h1)
__device__ __align__(16) __nv_bfloat16 g_yb0[ND];     // bf16 transformed features
__device__ __align__(16) __nv_bfloat16 g_yb1[ND];
__device__ __align__(16) __nv_bfloat16 g_yb2[ND];
__device__ __align__(16) __nv_bfloat16 g_yb3[ND];
__device__ __align__(16) __nv_bfloat16 g_WTb[9][D * D];  // bf16 pre-transposed weights [n][k]
__device__ float g_bc1[2 * D];
__device__ float g_bc2[D];

// Bucketed edge lists: group 0 = dst-type-0 (rel0 tag0, rel2 tag1) [reused by layer 2]
//                      group 1 = dst-type-1 (rel1 tag0, rel4 tag1)
__device__ int g_cnt[2][NN];
__device__ int g_rec[2][NN * CAP];

// pack two f32 into a bf16x2 word: low = a, high = b (PTX: cvt d, hi, lo)
__device__ __forceinline__ uint32_t bfpair(float a, float b) {
    uint32_t u;
    asm("cvt.rn.bf16x2.f32 %0, %1, %2;" : "=r"(u) : "f"(b), "f"(a));
    return u;
}

// ---------------- tiny kernels ----------------
__global__ void zero_cnt_kernel(float* o) {
    int i = blockIdx.x * blockDim.x + threadIdx.x;
    if (i < 2 * NN) ((int*)g_cnt)[i] = 0;
    if (i == 0) o[0] = 0.0f;
}

// x (fp32) -> g_xb (bf16), 4 floats per thread
__global__ void cvt_kernel(const float* __restrict__ x) {
    int i = blockIdx.x * blockDim.x + threadIdx.x;
    if (i < 3 * ND / 4) {
        float4 v = ((const float4*)x)[i];
        uint2 o;
        o.x = bfpair(v.x, v.y);
        o.y = bfpair(v.z, v.w);
        ((uint2*)g_xb)[i] = o;
    }
}

// segment s -> (rel k, group, tag):  s0:(0,0,0)  s1:(2,0,1)  s2:(1,1,0)  s3:(4,1,1)
__device__ __forceinline__ void seg_map(int s, int& k, int& grp, int& tag) {
    switch (s) {
        case 0:  k = 0; grp = 0; tag = 0; break;
        case 1:  k = 2; grp = 0; tag = 1; break;
        case 2:  k = 1; grp = 1; tag = 0; break;
        default: k = 4; grp = 1; tag = 1; break;
    }
}

// single pass: scatter edges into per-dst buckets
__global__ void fill_kernel(const int* __restrict__ edges) {
    int idx = blockIdx.x * blockDim.x + threadIdx.x;
    if (idx >= 4 * EE) return;
    int s = idx / EE, e = idx - s * EE;
    int k, grp, tag; seg_map(s, k, grp, tag);
    int src = edges[k * 2 * EE + e];
    int dst = edges[k * 2 * EE + EE + e];
    int pos = atomicAdd(&g_cnt[grp][dst], 1);
    if (pos < CAP)
        g_rec[grp][dst * CAP + pos] = (int)((unsigned)src | ((unsigned)tag << 31));
}

// Transpose (+ combine root pairs and biases) into g_WTb[9][n][k] (bf16).
__global__ void prep_kernel(const float* __restrict__ Wrel1, const float* __restrict__ brel1,
                            const float* __restrict__ Wroot1, const float* __restrict__ Wrel2,
                            const float* __restrict__ brel2, const float* __restrict__ Wroot2) {
    __shared__ float t[32][33];
    int j = blockIdx.z;
    const float* S0; const float* S1 = nullptr;
    switch (j) {
        case 0:  S0 = Wroot1;             S1 = Wroot1 + 2 * D * D; break;
        case 1:  S0 = Wroot1 + D * D;     S1 = Wroot1 + 4 * D * D; break;
        case 2:  S0 = Wrel1;              break;
        case 3:  S0 = Wrel1 + D * D;      break;
        case 4:  S0 = Wrel1 + 2 * D * D;  break;
        case 5:  S0 = Wrel1 + 4 * D * D;  break;
        case 6:  S0 = Wroot2;             S1 = Wroot2 + 2 * D * D; break;
        case 7:  S0 = Wrel2;              break;
        default: S0 = Wrel2 + 2 * D * D;  break;
    }
    int k0 = blockIdx.y * 32, n0 = blockIdx.x * 32;
    int tx = threadIdx.x, ty = threadIdx.y;     // 32 x 8
#pragma unroll
    for (int r = ty; r < 32; r += 8) {
        float v = S0[(size_t)(k0 + r) * D + n0 + tx];
        if (S1) v += S1[(size_t)(k0 + r) * D + n0 + tx];
        t[r][tx] = v;
    }
    __syncthreads();
    __nv_bfloat16* WT = g_WTb[j];
#pragma unroll
    for (int r = ty; r < 32; r += 8)
        WT[(size_t)(n0 + r) * D + k0 + tx] = __float2bfloat16_rn(t[tx][r]);

    if (blockIdx.x == 0 && blockIdx.y == 0 && j == 0) {
        int i = ty * 32 + tx;
        if (i < D) {
            g_bc1[i]     = brel1[i]         + brel1[2 * D + i];
            g_bc1[D + i] = brel1[D + i]     + brel1[4 * D + i];
            g_bc2[i]     = brel2[i]         + brel2[2 * D + i];
        }
    }
}

// ---------------- bf16 mma.sync GEMM, 4-stage cp.async + ldmatrix ----------------
// C[M,256] = A[M,256] @ W (+bias). CTA tile 128x128, BK=32, 4-stage ring.
// SMEM rows: 16 data words (32 bf16) + 4 pad = stride 20 words (80B).
// 8 rows under stride-20 hit banks {0,20,8,28,16,4,24,12}x4 = all 32 -> ldmatrix conflict-free.

#define TSTRIDE 20                        // words per SMEM row
#define TILEB   (128 * TSTRIDE * 4)       // bytes per tile buffer (10240)
#define NSTAGE  4
#define SMEM_GEMM (2 * NSTAGE * TILEB)    // 81920 bytes

__device__ __forceinline__ void cp16(uint32_t dst, const void* src, int sz) {
    asm volatile("cp.async.cg.shared.global [%0], [%1], 16, %2;"
                 :: "r"(dst), "l"(src), "r"(sz) : "memory");
}
__device__ __forceinline__ void cp_commit() {
    asm volatile("cp.async.commit_group;" ::: "memory");
}
__device__ __forceinline__ void ldm4(uint32_t& r0, uint32_t& r1, uint32_t& r2, uint32_t& r3,
                                     uint32_t addr) {
    asm volatile("ldmatrix.sync.aligned.m8n8.x4.shared.b16 {%0,%1,%2,%3}, [%4];"
                 : "=r"(r0), "=r"(r1), "=r"(r2), "=r"(r3) : "r"(addr));
}

__device__ __forceinline__ void mma_bf16(float* c, const uint32_t* a, const uint32_t* b) {
    asm volatile(
        "mma.sync.aligned.m16n8k16.row.col.f32.bf16.bf16.f32 "
        "{%0,%1,%2,%3}, {%4,%5,%6,%7}, {%8,%9}, {%0,%1,%2,%3};"
        : "+f"(c[0]), "+f"(c[1]), "+f"(c[2]), "+f"(c[3])
        : "r"(a[0]), "r"(a[1]), "r"(a[2]), "r"(a[3]), "r"(b[0]), "r"(b[1]));
}

template <bool BF16OUT>
__device__ __forceinline__ void gemm_body(const __nv_bfloat16* __restrict__ A,
                                          const __nv_bfloat16* __restrict__ WT,
                                          const float* __restrict__ bias,
                                          float* __restrict__ Cf,
                                          __nv_bfloat16* __restrict__ Cb) {
    extern __shared__ __align__(16) uint32_t smem[];
    const uint32_t sbase = (uint32_t)__cvta_generic_to_shared(smem);

    const int tid  = threadIdx.x;
    const int wid  = tid >> 5;
    const int lane = tid & 31;
    const int gid  = lane >> 2;
    const int tig  = lane & 3;
    const int m0 = blockIdx.x * 128;
    const int n0 = blockIdx.y * 128;
    const int wm = (wid & 3) * 32;
    const int wn = (wid >> 2) * 64;

    const int arow = tid >> 2;
    const int ac   = tid & 3;

    uint32_t aoff[2];
#pragma unroll
    for (int mt = 0; mt < 2; mt++) {
        int row = wm + mt * 16 + ((lane >> 3) & 1) * 8 + (lane & 7);
        aoff[mt] = (uint32_t)(row * TSTRIDE + (lane >> 4) * 4) * 4;
    }
    uint32_t boff[4];
#pragma unroll
    for (int p = 0; p < 4; p++) {
        int row = wn + p * 16 + ((lane >> 4) & 1) * 8 + (lane & 7);
        boff[p] = (uint32_t)(row * TSTRIDE + ((lane >> 3) & 1) * 4) * 4;
    }

    auto stage = [&](int kc, int b) {
        uint32_t sa = sbase + (uint32_t)b * TILEB;
        uint32_t sb = sbase + (uint32_t)(NSTAGE + b) * TILEB;
#pragma unroll
        for (int i = 0; i < 2; i++) {
            int row = arow + i * 64;
            int m = m0 + row;
            const void* src = A + (size_t)m * D + kc * 32 + ac * 8;
            cp16(sa + (uint32_t)(row * 80 + ac * 16), src, m < NN ? 16 : 0);
        }
#pragma unroll
        for (int i = 0; i < 2; i++) {
            int row = arow + i * 64;
            const void* src = WT + (size_t)(n0 + row) * D + kc * 32 + ac * 8;
            cp16(sb + (uint32_t)(row * 80 + ac * 16), src, 16);
        }
        cp_commit();
    };

    float acc[2][8][4];
#pragma unroll
    for (int mt = 0; mt < 2; mt++)
#pragma unroll
        for (int nt = 0; nt < 8; nt++)
#pragma unroll
            for (int q = 0; q < 4; q++) acc[mt][nt][q] = 0.0f;

    stage(0, 0);
    stage(1, 1);
    stage(2, 2);

    for (int kc = 0; kc < 8; kc++) {
        const int buf = kc & 3;
        if (kc < 6)      asm volatile("cp.async.wait_group 2;" ::: "memory");
        else if (kc == 6) asm volatile("cp.async.wait_group 1;" ::: "memory");
        else             asm volatile("cp.async.wait_group 0;" ::: "memory");
        __syncthreads();

        const uint32_t pa = sbase + (uint32_t)buf * TILEB;
        const uint32_t pb = sbase + (uint32_t)(NSTAGE + buf) * TILEB;
#pragma unroll
        for (int ks = 0; ks < 2; ks++) {
            const uint32_t kb = ks * 32;
            uint32_t af[2][4], bf[8][2];
#pragma unroll
            for (int mt = 0; mt < 2; mt++)
                ldm4(af[mt][0], af[mt][1], af[mt][2], af[mt][3], pa + aoff[mt] + kb);
#pragma unroll
            for (int p = 0; p < 4; p++)
                ldm4(bf[2 * p][0], bf[2 * p][1], bf[2 * p + 1][0], bf[2 * p + 1][1],
                     pb + boff[p] + kb);
#pragma unroll
            for (int mt = 0; mt < 2; mt++)
#pragma unroll
                for (int nt = 0; nt < 8; nt++)
                    mma_bf16(acc[mt][nt], af[mt], bf[nt]);
        }
        int nk = kc + 3;
        if (nk < 8) stage(nk, nk & 3);
    }

#pragma unroll
    for (int mt = 0; mt < 2; mt++) {
        int m_lo = m0 + wm + mt * 16 + gid;
        int m_hi = m_lo + 8;
#pragma unroll
        for (int nt = 0; nt < 8; nt++) {
            int n = n0 + wn + nt * 8 + tig * 2;
            if (BF16OUT) {
                if (m_lo < NN)
                    *(uint32_t*)(Cb + (size_t)m_lo * D + n) =
                        bfpair(acc[mt][nt][0], acc[mt][nt][1]);
                if (m_hi < NN)
                    *(uint32_t*)(Cb + (size_t)m_hi * D + n) =
                        bfpair(acc[mt][nt][2], acc[mt][nt][3]);
            } else {
                float b0 = bias ? bias[n] : 0.f;
                float b1 = bias ? bias[n + 1] : 0.f;
                if (m_lo < NN)
                    *(float2*)(Cf + (size_t)m_lo * D + n) =
                        make_float2(acc[mt][nt][0] + b0, acc[mt][nt][1] + b1);
                if (m_hi < NN)
                    *(float2*)(Cf + (size_t)m_hi * D + n) =
                        make_float2(acc[mt][nt][2] + b0, acc[mt][nt][3] + b1);
            }
        }
    }
}

// ---- gemm1 split by dependency group ----
// g1a (stream 0): everything group-0 gather needs: h0, yb0, yb1
__global__ __launch_bounds__(256, 2) void gemm1a_tc() {
    switch (blockIdx.z) {
        case 0:  gemm_body<false>(g_xb,      g_WTb[0], g_bc1, g_h0, nullptr); break;
        case 1:  gemm_body<true >(g_xb,      g_WTb[2], nullptr, nullptr, g_yb0); break;
        default: gemm_body<true >(g_xb + ND, g_WTb[4], nullptr, nullptr, g_yb1); break;
    }
}
// g1b (stream 1): group-1 needs: h1, yb2, yb3
__global__ __launch_bounds__(256, 2) void gemm1b_tc() {
    switch (blockIdx.z) {
        case 0:  gemm_body<false>(g_xb + ND,     g_WTb[1], g_bc1 + D, g_h1, nullptr); break;
        case 1:  gemm_body<true >(g_xb,          g_WTb[3], nullptr, nullptr, g_yb2); break;
        default: gemm_body<true >(g_xb + 2 * ND, g_WTb[5], nullptr, nullptr, g_yb3); break;
    }
}
// gemm2a (stream 0): o2 root + yb0' (both read hb0)
__global__ __launch_bounds__(256, 2) void gemm2a_tc() {
    if (blockIdx.z == 0) gemm_body<false>(g_hb0, g_WTb[6], g_bc2, g_o2, nullptr);
    else                 gemm_body<true >(g_hb0, g_WTb[7], nullptr, nullptr, g_yb0);
}
// gemm2b (stream 1): yb1' (reads hb1; overwrites yb1 -> must wait gather1_g0)
__global__ __launch_bounds__(256, 2) void gemm2b_tc() {
    gemm_body<true>(g_hb1, g_WTb[8], nullptr, nullptr, g_yb1);
}

// ---------------- bucket gather: one warp per dst node ----------------
__device__ __forceinline__ void accum_row(float* acc, const __nv_bfloat16* __restrict__ y0,
                                          const __nv_bfloat16* __restrict__ y1,
                                          int rec, int lane) {
    const __nv_bfloat16* yb = (rec < 0) ? y1 : y0;
    int src = rec & 0x7fffffff;
    uint4 v = *(const uint4*)(yb + (size_t)src * D + lane * 8);
    const __nv_bfloat162* p = (const __nv_bfloat162*)&v;
    float2 f0 = __bfloat1622float2(p[0]);
    float2 f1 = __bfloat1622float2(p[1]);
    float2 f2 = __bfloat1622float2(p[2]);
    float2 f3 = __bfloat1622float2(p[3]);
    acc[0] += f0.x; acc[1] += f0.y; acc[2] += f1.x; acc[3] += f1.y;
    acc[4] += f2.x; acc[5] += f2.y; acc[6] += f3.x; acc[7] += f3.y;
}

__device__ __forceinline__ void gather_accum(int grp, int node,
                                             const __nv_bfloat16* __restrict__ y0,
                                             const __nv_bfloat16* __restrict__ y1,
                                             float* acc, int lane) {
    const int* __restrict__ recs = g_rec[grp] + node * CAP;
    int cnt = g_cnt[grp][node];
    if (cnt > CAP) cnt = CAP;

    for (int base = 0; base < cnt; base += 32) {
        int m = cnt - base;
        if (m > 32) m = 32;
        int rec = 0;
        if (lane < m) rec = recs[base + lane];
        int j = 0;
        for (; j + 4 <= m; j += 4) {
            int r0 = __shfl_sync(0xFFFFFFFFu, rec, j);
            int r1 = __shfl_sync(0xFFFFFFFFu, rec, j + 1);
            int r2 = __shfl_sync(0xFFFFFFFFu, rec, j + 2);
            int r3 = __shfl_sync(0xFFFFFFFFu, rec, j + 3);
            accum_row(acc, y0, y1, r0, lane);
            accum_row(acc, y0, y1, r1, lane);
            accum_row(acc, y0, y1, r2, lane);
            accum_row(acc, y0, y1, r3, lane);
        }
        for (; j < m; j++) {
            int r = __shfl_sync(0xFFFFFFFFu, rec, j);
            accum_row(acc, y0, y1, r, lane);
        }
    }
}

// layer-1 gather for ONE group: h = root + agg; write bf16 relu(h)
template <int GRP>
__device__ __forceinline__ void gather1_body() {
    int node = (blockIdx.x * blockDim.x + threadIdx.x) >> 5;   // 0..NN-1
    int lane = threadIdx.x & 31;

    float acc[8] = {0.f, 0.f, 0.f, 0.f, 0.f, 0.f, 0.f, 0.f};
    if (GRP == 0) gather_accum(0, node, g_yb0, g_yb1, acc, lane);
    else          gather_accum(1, node, g_yb2, g_yb3, acc, lane);

    const float* rootp = (GRP == 0 ? g_h0 : g_h1) + (size_t)node * D + lane * 8;
    float4 a = *(const float4*)rootp;
    float4 b = *(const float4*)(rootp + 4);
    uint4 w;
    w.x = bfpair(fmaxf(a.x + acc[0], 0.f), fmaxf(a.y + acc[1], 0.f));
    w.y = bfpair(fmaxf(a.z + acc[2], 0.f), fmaxf(a.w + acc[3], 0.f));
    w.z = bfpair(fmaxf(b.x + acc[4], 0.f), fmaxf(b.y + acc[5], 0.f));
    w.w = bfpair(fmaxf(b.z + acc[6], 0.f), fmaxf(b.w + acc[7], 0.f));
    __nv_bfloat16* hb = GRP == 0 ? g_hb0 : g_hb1;
    *(uint4*)(hb + (size_t)node * D + lane * 8) = w;
}

__global__ void gather1_g0_kernel() { gather1_body<0>(); }
__global__ void gather1_g1_kernel() { gather1_body<1>(); }

// ---------------- fused layer-2 gather + loss ----------------
__global__ void gather2_loss_kernel(const int* __restrict__ y, float* __restrict__ out) {
    int gw   = (blockIdx.x * blockDim.x + threadIdx.x) >> 5;   // 0..19999
    int lane = threadIdx.x & 31;

    float acc[8] = {0.f, 0.f, 0.f, 0.f, 0.f, 0.f, 0.f, 0.f};
    gather_accum(0, gw, g_yb0, g_yb1, acc, lane);

    const float* rp = g_o2 + (size_t)gw * D + lane * 8;
    float4 a = *(const float4*)rp;
    float4 b = *(const float4*)(rp + 4);
    float v[8];
    v[0] = a.x + acc[0]; v[1] = a.y + acc[1]; v[2] = a.z + acc[2]; v[3] = a.w + acc[3];
    v[4] = b.x + acc[4]; v[5] = b.y + acc[5]; v[6] = b.z + acc[6]; v[7] = b.w + acc[7];

    float m = v[0];
#pragma unroll
    for (int i = 1; i < 8; i++) m = fmaxf(m, v[i]);
#pragma unroll
    for (int o = 16; o; o >>= 1) m = fmaxf(m, __shfl_xor_sync(0xFFFFFFFFu, m, o));

    float s = 0.0f;
#pragma unroll
    for (int i = 0; i < 8; i++) s += expf(v[i] - m);
#pragma unroll
    for (int o = 16; o; o >>= 1) s += __shfl_xor_sync(0xFFFFFFFFu, s, o);

    int yy = y[gw];
    float tv = v[0];
#pragma unroll
    for (int j = 1; j < 8; j++) tv = ((yy & 7) == j) ? v[j] : tv;
    float target = __shfl_sync(0xFFFFFFFFu, tv, yy >> 3);

    float nll = (m + logf(s)) - target;

    __shared__ float partial[8];
    if (lane == 0) partial[threadIdx.x >> 5] = nll;
    __syncthreads();
    if (threadIdx.x == 0) {
        float t = 0.0f;
#pragma unroll
        for (int i = 0; i < 8; i++) t += partial[i];
        atomicAdd(out, t * (1.0f / (float)NN));
    }
}

// ---------------- launch: dual-stream fork/join (graph-capture-safe) ----------------
extern "C" void kernel_launch(void* const* d_in, const int* in_sizes, int n_in,
                              void* d_out, int out_size) {
    const float* x      = (const float*)d_in[0];
    const int*   edges  = (const int*)d_in[1];
    const int*   y      = (const int*)d_in[2];
    const float* Wrel1  = (const float*)d_in[3];
    const float* brel1  = (const float*)d_in[4];
    const float* Wroot1 = (const float*)d_in[5];
    const float* Wrel2  = (const float*)d_in[6];
    const float* brel2  = (const float*)d_in[7];
    const float* Wroot2 = (const float*)d_in[8];
    float* out = (float*)d_out;

    static cudaStream_t s1 = nullptr;
    static cudaEvent_t evZ, evP, evF, evH, evG;
    if (!s1) {
        cudaStreamCreateWithFlags(&s1, cudaStreamNonBlocking);
        cudaEventCreateWithFlags(&evZ, cudaEventDisableTiming);
        cudaEventCreateWithFlags(&evP, cudaEventDisableTiming);
        cudaEventCreateWithFlags(&evF, cudaEventDisableTiming);
        cudaEventCreateWithFlags(&evH, cudaEventDisableTiming);
        cudaEventCreateWithFlags(&evG, cudaEventDisableTiming);
    }
    cudaFuncSetAttribute(gemm1a_tc, cudaFuncAttributeMaxDynamicSharedMemorySize, SMEM_GEMM);
    cudaFuncSetAttribute(gemm1b_tc, cudaFuncAttributeMaxDynamicSharedMemorySize, SMEM_GEMM);
    cudaFuncSetAttribute(gemm2a_tc, cudaFuncAttributeMaxDynamicSharedMemorySize, SMEM_GEMM);
    cudaFuncSetAttribute(gemm2b_tc, cudaFuncAttributeMaxDynamicSharedMemorySize, SMEM_GEMM);

    const int MT = (NN + 127) / 128;   // 157 M-tiles
    cudaStream_t s0 = 0;

    // s0: counters+out zero -> fork
    zero_cnt_kernel<<<(2 * NN + 255) / 256, 256, 0, s0>>>(out);
    cudaEventRecord(evZ, s0);

    // s1: fill buckets (needs zeroed counters only)
    cudaStreamWaitEvent(s1, evZ, 0);
    fill_kernel<<<(4 * EE + 255) / 256, 256, 0, s1>>>(edges);
    cudaEventRecord(evF, s1);

    // s0: cvt + prep (concurrent with fill)
    cvt_kernel<<<(3 * ND / 4 + 255) / 256, 256, 0, s0>>>(x);
    prep_kernel<<<dim3(8, 8, 9), dim3(32, 8), 0, s0>>>(Wrel1, brel1, Wroot1,
                                                       Wrel2, brel2, Wroot2);
    cudaEventRecord(evP, s0);

    // s0 chain: gemm1a -> gather1_g0 -> gemm2a
    gemm1a_tc<<<dim3(MT, 2, 3), 256, SMEM_GEMM, s0>>>();
    // s1 chain: gemm1b -> gather1_g1 (needs cvt+prep)
    cudaStreamWaitEvent(s1, evP, 0);
    gemm1b_tc<<<dim3(MT, 2, 3), 256, SMEM_GEMM, s1>>>();
    gather1_g1_kernel<<<(NN * 32) / 256, 256, 0, s1>>>();

    cudaStreamWaitEvent(s0, evF, 0);              // gather1_g0 needs fill
    gather1_g0_kernel<<<(NN * 32) / 256, 256, 0, s0>>>();
    cudaEventRecord(evH, s0);                     // yb0/yb1 consumed (layer-1 values)

    gemm2a_tc<<<dim3(MT, 2, 2), 256, SMEM_GEMM, s0>>>();

    // s1: gemm2b overwrites yb1 -> must wait for gather1_g0's reads (evH)
    cudaStreamWaitEvent(s1, evH, 0);
    gemm2b_tc<<<dim3(MT, 2, 1), 256, SMEM_GEMM, s1>>>();
    cudaEventRecord(evG, s1);

    // s0: final fused gather+loss (joins s1)
    cudaStreamWaitEvent(s0, evG, 0);
    gather2_loss_kernel<<<NN / 8, 256, 0, s0>>>(y, out);
}